// round 1
// baseline (speedup 1.0000x reference)
#include <cuda_runtime.h>
#include <cstdint>

#define B_SZ 8192
#define HID  1024
#define PROJ 512
#define KSEL 4096

// ---------------- scratch (device globals: no allocs allowed) ----------------
__device__ float g_feat [B_SZ * HID];                 // adapter out
__device__ float g_hbuf [B_SZ * HID];                 // relu hidden (reused)
__device__ float g_mproj[B_SZ * PROJ];
__device__ float g_iproj[B_SZ * PROJ];
__device__ float g_sim  [(size_t)B_SZ * B_SZ];        // 256 MB
__device__ float g_ce   [2 * B_SZ];

// ---------------- GEMM: C = scale * (A @ op(B) + bias), optional ReLU --------
// A: MxK row-major. TRANS_B: B is NxK row-major (C=A@B^T), else B KxN row-major.
// All of M,N multiples of 128; K multiple of 16.
constexpr int BM = 128, BN = 128, BK = 16;

template <bool TRANS_B, bool RELU, bool BIAS>
__global__ __launch_bounds__(256)
void gemm_kernel(const float* __restrict__ A, const float* __restrict__ Bm,
                 const float* __restrict__ bias, float* __restrict__ C,
                 int M, int N, int K, float scale)
{
    __shared__ float As[BK][BM + 4];
    __shared__ float Bs[BK][BN + 4];
    const int bm = blockIdx.y * BM;
    const int bn = blockIdx.x * BN;
    const int tid  = threadIdx.x;
    const int trow = tid >> 4;   // 0..15
    const int tcol = tid & 15;   // 0..15

    float acc[8][8];
#pragma unroll
    for (int i = 0; i < 8; i++)
#pragma unroll
        for (int j = 0; j < 8; j++) acc[i][j] = 0.f;

    for (int k0 = 0; k0 < K; k0 += BK) {
        // --- load A tile (BM x BK), float4 along K, store transposed ---
#pragma unroll
        for (int s = tid; s < BM * BK / 4; s += 256) {
            int m = s >> 2, k4 = s & 3;
            float4 v = *(const float4*)(A + (size_t)(bm + m) * K + k0 + k4 * 4);
            As[k4 * 4 + 0][m] = v.x; As[k4 * 4 + 1][m] = v.y;
            As[k4 * 4 + 2][m] = v.z; As[k4 * 4 + 3][m] = v.w;
        }
        if (TRANS_B) {
#pragma unroll
            for (int s = tid; s < BN * BK / 4; s += 256) {
                int n = s >> 2, k4 = s & 3;
                float4 v = *(const float4*)(Bm + (size_t)(bn + n) * K + k0 + k4 * 4);
                Bs[k4 * 4 + 0][n] = v.x; Bs[k4 * 4 + 1][n] = v.y;
                Bs[k4 * 4 + 2][n] = v.z; Bs[k4 * 4 + 3][n] = v.w;
            }
        } else {
#pragma unroll
            for (int s = tid; s < BK * BN / 4; s += 256) {
                int kk = s >> 5, n4 = s & 31;
                float4 v = *(const float4*)(Bm + (size_t)(k0 + kk) * N + bn + n4 * 4);
                *(float4*)&Bs[kk][n4 * 4] = v;
            }
        }
        __syncthreads();
#pragma unroll
        for (int kk = 0; kk < BK; kk++) {
            float a[8], b[8];
            *(float4*)(a)     = *(const float4*)&As[kk][trow * 8];
            *(float4*)(a + 4) = *(const float4*)&As[kk][trow * 8 + 4];
            *(float4*)(b)     = *(const float4*)&Bs[kk][tcol * 8];
            *(float4*)(b + 4) = *(const float4*)&Bs[kk][tcol * 8 + 4];
#pragma unroll
            for (int i = 0; i < 8; i++)
#pragma unroll
                for (int j = 0; j < 8; j++)
                    acc[i][j] = fmaf(a[i], b[j], acc[i][j]);
        }
        __syncthreads();
    }

    const int m0 = bm + trow * 8, n0 = bn + tcol * 8;
    float bv[8];
#pragma unroll
    for (int j = 0; j < 8; j++) bv[j] = BIAS ? bias[n0 + j] : 0.f;
#pragma unroll
    for (int i = 0; i < 8; i++) {
        float out[8];
#pragma unroll
        for (int j = 0; j < 8; j++) {
            float v = (acc[i][j] + bv[j]) * scale;
            if (RELU) v = fmaxf(v, 0.f);
            out[j] = v;
        }
        float* dst = C + (size_t)(m0 + i) * N + n0;
        *(float4*)dst       = *(float4*)out;
        *(float4*)(dst + 4) = *(float4*)(out + 4);
    }
}

// ---------------- row L2 normalize (rows of PROJ=512) ------------------------
__global__ void normalize_kernel(float* __restrict__ x)
{
    __shared__ float red[128];
    const int row = blockIdx.x;
    const int tid = threadIdx.x;
    float* p = x + (size_t)row * PROJ;
    float s = 0.f;
    for (int j = tid; j < PROJ; j += 128) { float v = p[j]; s += v * v; }
    red[tid] = s; __syncthreads();
    for (int off = 64; off > 0; off >>= 1) {
        if (tid < off) red[tid] += red[tid + off];
        __syncthreads();
    }
    const float r = 1.f / sqrtf(red[0]);
    for (int j = tid; j < PROJ; j += 128) p[j] *= r;
}

// ---------------- mining + weighted log-softmax loss per row -----------------
__device__ __forceinline__ unsigned mono(float f)
{
    unsigned u = __float_as_uint(f);
    return (u & 0x80000000u) ? ~u : (u | 0x80000000u);  // order-preserving
}

__global__ __launch_bounds__(256)
void mine_loss_kernel(const float* __restrict__ sim, const float* __restrict__ mw,
                      float* __restrict__ ce_out, int modal)
{
    __shared__ float    sh[B_SZ];      // 32 KB row cache
    __shared__ unsigned hist[256];
    __shared__ float    red[256];
    __shared__ unsigned s_prefix;
    __shared__ int      s_kth;

    const int row  = blockIdx.x;
    const int tid  = threadIdx.x;
    const int lane = tid & 31;
    const float* srow = sim + (size_t)row * B_SZ;

    for (int j = tid; j < B_SZ; j += 256) sh[j] = srow[j];
    __syncthreads();

    // radix select: KSEL-th largest key (excluded entries -> key 0)
    unsigned prefix = 0, pmask = 0;
    int kth = KSEL;
#pragma unroll
    for (int pass = 3; pass >= 0; --pass) {
        const int shift = pass * 8;
        hist[tid] = 0;
        __syncthreads();
        for (int j = tid; j < B_SZ; j += 256) {   // uniform trip count: 32
            float s = sh[j];
            unsigned u = (j == row || s > 9.0f) ? 0u : mono(s);
            unsigned bin = ((u & pmask) == prefix) ? ((u >> shift) & 255u)
                                                   : 0xFFFFFFFFu;
            unsigned peers = __match_any_sync(0xFFFFFFFFu, bin);
            if (bin != 0xFFFFFFFFu && lane == (unsigned)(__ffs(peers) - 1))
                atomicAdd(&hist[bin], (unsigned)__popc(peers));
        }
        __syncthreads();
        if (tid == 0) {
            int acc = 0, b = 255;
            for (;; --b) { acc += (int)hist[b]; if (acc >= kth || b == 0) break; }
            s_prefix = prefix | ((unsigned)b << shift);
            s_kth    = kth - (acc - (int)hist[b]);
        }
        __syncthreads();
        prefix = s_prefix; kth = s_kth;
        pmask |= (0xFFu << shift);
    }
    const unsigned thr = prefix;   // key of the KSEL-th largest

    // weights + in-place weighted values; row max
    float vmax = -3.402823466e38f;
    for (int j = tid; j < B_SZ; j += 256) {
        float s = sh[j];
        bool diag  = (j == row);
        bool noise = (!diag) && (s > 9.0f);
        float w;
        if (noise)                              w = 0.5f;
        else if (!diag && mono(s) >= thr)       w = 1.5f;
        else                                    w = 1.0f;
        float v = s * w;
        sh[j] = v;
        vmax = fmaxf(vmax, v);
    }
    red[tid] = vmax; __syncthreads();
    for (int off = 128; off > 0; off >>= 1) {
        if (tid < off) red[tid] = fmaxf(red[tid], red[tid + off]);
        __syncthreads();
    }
    const float vm = red[0];
    __syncthreads();

    float ssum = 0.f;
    for (int j = tid; j < B_SZ; j += 256) ssum += expf(sh[j] - vm);
    red[tid] = ssum; __syncthreads();
    for (int off = 128; off > 0; off >>= 1) {
        if (tid < off) red[tid] += red[tid + off];
        __syncthreads();
    }
    if (tid == 0) {
        float lse = vm + logf(red[0]);
        float ce  = lse - sh[row];                 // -(v_ii - lse)
        ce_out[modal * B_SZ + row] = ce * mw[(size_t)row * 2 + modal];
    }
}

// ---------------- final reduction -> scalar ----------------------------------
__global__ void finalize_kernel(const float* __restrict__ ce, float* __restrict__ out)
{
    __shared__ float red[256];
    const int tid = threadIdx.x;
    float s = 0.f;
    for (int j = tid; j < 2 * B_SZ; j += 256) s += ce[j];
    red[tid] = s; __syncthreads();
    for (int off = 128; off > 0; off >>= 1) {
        if (tid < off) red[tid] += red[tid + off];
        __syncthreads();
    }
    if (tid == 0) out[0] = red[0] * (0.5f / (float)B_SZ);
}

// ---------------- launch ------------------------------------------------------
extern "C" void kernel_launch(void* const* d_in, const int* in_sizes, int n_in,
                              void* d_out, int out_size)
{
    const float* id_emb = (const float*)d_in[0];
    const float* text   = (const float*)d_in[1];
    const float* vis    = (const float*)d_in[2];
    const float* mw     = (const float*)d_in[3];
    const float* Wa_t = (const float*)d_in[4];  const float* ba_t = (const float*)d_in[5];
    const float* Wa_v = (const float*)d_in[6];  const float* ba_v = (const float*)d_in[7];
    const float* W1_t = (const float*)d_in[8];  const float* b1_t = (const float*)d_in[9];
    const float* W2_t = (const float*)d_in[10]; const float* b2_t = (const float*)d_in[11];
    const float* W1_v = (const float*)d_in[12]; const float* b1_v = (const float*)d_in[13];
    const float* W2_v = (const float*)d_in[14]; const float* b2_v = (const float*)d_in[15];

    float *feat, *hbuf, *mproj, *iproj, *sim, *ce;
    cudaGetSymbolAddress((void**)&feat,  g_feat);
    cudaGetSymbolAddress((void**)&hbuf,  g_hbuf);
    cudaGetSymbolAddress((void**)&mproj, g_mproj);
    cudaGetSymbolAddress((void**)&iproj, g_iproj);
    cudaGetSymbolAddress((void**)&sim,   g_sim);
    cudaGetSymbolAddress((void**)&ce,    g_ce);

    const float inv_temp = 10.0f;   // 1 / TEMP

    struct Modal {
        const float* f; int kf;
        const float *Wa, *ba, *W1, *b1, *W2, *b2;
    };
    const Modal ms[2] = {
        { text,  768, Wa_t, ba_t, W1_t, b1_t, W2_t, b2_t },   // modal 0 = text
        { vis,  2048, Wa_v, ba_v, W1_v, b1_v, W2_v, b2_v },   // modal 1 = visual
    };

    const dim3 blk(256);
    for (int m = 0; m < 2; m++) {
        // adapter: feat = f @ Wa + ba
        gemm_kernel<false, false, true><<<dim3(HID / BN, B_SZ / BM), blk>>>(
            ms[m].f, ms[m].Wa, ms[m].ba, feat, B_SZ, HID, ms[m].kf, 1.f);
        // modal projector
        gemm_kernel<false, true, true><<<dim3(HID / BN, B_SZ / BM), blk>>>(
            feat, ms[m].W1, ms[m].b1, hbuf, B_SZ, HID, HID, 1.f);
        gemm_kernel<false, false, true><<<dim3(PROJ / BN, B_SZ / BM), blk>>>(
            hbuf, ms[m].W2, ms[m].b2, mproj, B_SZ, PROJ, HID, 1.f);
        normalize_kernel<<<B_SZ, 128>>>(mproj);
        // id projector (same weights as this modality's projector)
        gemm_kernel<false, true, true><<<dim3(HID / BN, B_SZ / BM), blk>>>(
            id_emb, ms[m].W1, ms[m].b1, hbuf, B_SZ, HID, HID, 1.f);
        gemm_kernel<false, false, true><<<dim3(PROJ / BN, B_SZ / BM), blk>>>(
            hbuf, ms[m].W2, ms[m].b2, iproj, B_SZ, PROJ, HID, 1.f);
        normalize_kernel<<<B_SZ, 128>>>(iproj);
        // sim = (iproj @ mproj^T) / TEMP
        gemm_kernel<true, false, false><<<dim3(B_SZ / BN, B_SZ / BM), blk>>>(
            iproj, mproj, nullptr, sim, B_SZ, B_SZ, PROJ, inv_temp);
        // hard-negative mining + weighted CE
        mine_loss_kernel<<<B_SZ, 256>>>(sim, mw, ce, m);
    }
    finalize_kernel<<<1, 256>>>(ce, (float*)d_out);
}

// round 4
// speedup vs baseline: 3.3673x; 3.3673x over previous
#include <cuda_runtime.h>
#include <cuda_bf16.h>
#include <cstdint>

#define B_SZ 8192
#define HID  1024
#define PROJ 512
#define KSEL 4096

// ======================= helpers =============================================
__device__ __forceinline__ uint32_t smem_to_u32(const void* p) {
    uint32_t a;
    asm("{ .reg .u64 t; cvta.to.shared.u64 t, %1; cvt.u32.u64 %0, t; }"
        : "=r"(a) : "l"(p));
    return a;
}
#define SW128(off) ((off) ^ (((off) >> 3) & 0x70))

__device__ __forceinline__ void cp_async16(uint32_t dst, const void* src) {
    asm volatile("cp.async.cg.shared.global [%0], [%1], 16;"
                 :: "r"(dst), "l"(src) : "memory");
}
__device__ __forceinline__ void ldsm_x4(uint32_t& r0, uint32_t& r1,
                                        uint32_t& r2, uint32_t& r3, uint32_t addr) {
    asm volatile("ldmatrix.sync.aligned.m8n8.x4.shared.b16 {%0,%1,%2,%3}, [%4];"
                 : "=r"(r0), "=r"(r1), "=r"(r2), "=r"(r3) : "r"(addr));
}
__device__ __forceinline__ void mma_bf16(float* c, const uint32_t* a,
                                         uint32_t b0, uint32_t b1) {
    asm volatile(
        "mma.sync.aligned.m16n8k16.row.col.f32.bf16.bf16.f32 "
        "{%0,%1,%2,%3}, {%4,%5,%6,%7}, {%8,%9}, {%0,%1,%2,%3};"
        : "+f"(c[0]), "+f"(c[1]), "+f"(c[2]), "+f"(c[3])
        : "r"(a[0]), "r"(a[1]), "r"(a[2]), "r"(a[3]), "r"(b0), "r"(b1));
}

// ======================= scratch (device globals) ============================
__device__ __align__(16) __nv_bfloat16 g_Wa_t[HID * 768];
__device__ __align__(16) __nv_bfloat16 g_Wa_v[HID * 2048];
__device__ __align__(16) __nv_bfloat16 g_W1_t[HID * HID];
__device__ __align__(16) __nv_bfloat16 g_W1_v[HID * HID];
__device__ __align__(16) __nv_bfloat16 g_W2_t[PROJ * HID];
__device__ __align__(16) __nv_bfloat16 g_W2_v[PROJ * HID];
__device__ __align__(16) __nv_bfloat16 g_id_bf[B_SZ * HID];
__device__ __align__(16) __nv_bfloat16 g_in_bf[B_SZ * 2048];
__device__ __align__(16) __nv_bfloat16 g_feat_bf[B_SZ * HID];
__device__ __align__(16) __nv_bfloat16 g_h_bf[B_SZ * HID];
__device__ __align__(16) float         g_projf[B_SZ * PROJ];
__device__ __align__(16) __nv_bfloat16 g_mproj[B_SZ * PROJ];
__device__ __align__(16) __nv_bfloat16 g_iproj[B_SZ * PROJ];
__device__ float g_sim[(size_t)B_SZ * B_SZ];
__device__ float g_ce[2 * B_SZ];

// ======================= HMMA GEMM ===========================================
// C[M,N] = epi(A[M,K] @ Bw[N,K]^T). bf16 in, fp32 accum.
// CTA tile 128x128, 8 warps of 64x32, K-tile 64 (bf16), double-buffered cp.async.
static constexpr int TC_DSMEM = 64 * 1024 + 1024;

template <bool RELU, bool BIAS, bool OUT_BF16>
__global__ __launch_bounds__(256)
void hmma_gemm(const __nv_bfloat16* __restrict__ A, const __nv_bfloat16* __restrict__ Bw,
               const float* __restrict__ bias, void* __restrict__ Cout,
               int M, int N, int K, float scale)
{
    extern __shared__ char dsm[];
    const uint32_t base_u  = smem_to_u32(dsm);
    const uint32_t tiles_u = (base_u + 1023u) & ~1023u;

    const int tid  = threadIdx.x;
    const int wid  = tid >> 5, lane = tid & 31;
    const int wm   = wid >> 2, wn = wid & 3;          // 2 x 4 warp grid
    const int bm   = blockIdx.y * 128, bn = blockIdx.x * 128;
    const int nsteps = K >> 6;

    float acc[4][4][4];
#pragma unroll
    for (int i = 0; i < 4; i++)
#pragma unroll
        for (int j = 0; j < 4; j++)
#pragma unroll
            for (int r = 0; r < 4; r++) acc[i][j][r] = 0.f;

    // FIXED loader: full tile coverage.
    // 32 base rows (tid>>3) x 8 chunks (tid&7), h-loop strides rows by 32:
    // 256 thr * 4 rows * 16B = 16KB per tile, A and B each.
    const int lr = tid >> 3;         // 0..31
    const int lc = tid & 7;          // 16B chunk within 128B row

    auto load_stage = [&](int buf, int k0) {
        const uint32_t tA = tiles_u + (uint32_t)buf * 32768u;
        const uint32_t tB = tA + 16384u;
#pragma unroll
        for (int h = 0; h < 4; h++) {
            int r = lr + h * 32;
            uint32_t sw = SW128((uint32_t)(r * 128 + lc * 16));
            cp_async16(tA + sw, A  + (size_t)(bm + r) * K + k0 + lc * 8);
            cp_async16(tB + sw, Bw + (size_t)(bn + r) * K + k0 + lc * 8);
        }
        asm volatile("cp.async.commit_group;" ::: "memory");
    };

    load_stage(0, 0);

    for (int s = 0; s < nsteps; ++s) {
        const int b = s & 1;
        if (s + 1 < nsteps) {
            load_stage(b ^ 1, (s + 1) << 6);
            asm volatile("cp.async.wait_group 1;" ::: "memory");
        } else {
            asm volatile("cp.async.wait_group 0;" ::: "memory");
        }
        __syncthreads();

        const uint32_t tA = tiles_u + (uint32_t)b * 32768u;
        const uint32_t tB = tA + 16384u;

#pragma unroll
        for (int kk = 0; kk < 4; ++kk) {
            const int kb = kk * 32;                    // byte offset of k16 slice
            uint32_t a[4][4];
#pragma unroll
            for (int mt = 0; mt < 4; ++mt) {
                int row  = wm * 64 + mt * 16 + (lane & 15);
                int colb = kb + ((lane >> 4) << 4);
                ldsm_x4(a[mt][0], a[mt][1], a[mt][2], a[mt][3],
                        tA + SW128((uint32_t)(row * 128 + colb)));
            }
            uint32_t bf[2][4];
#pragma unroll
            for (int np = 0; np < 2; ++np) {
                int nrow = wn * 32 + np * 16 + (lane & 7) + ((lane >> 4) << 3);
                int colb = kb + (((lane >> 3) & 1) << 4);
                ldsm_x4(bf[np][0], bf[np][1], bf[np][2], bf[np][3],
                        tB + SW128((uint32_t)(nrow * 128 + colb)));
            }
#pragma unroll
            for (int mt = 0; mt < 4; ++mt)
#pragma unroll
                for (int nt = 0; nt < 4; ++nt)
                    mma_bf16(acc[mt][nt], a[mt],
                             bf[nt >> 1][(nt & 1) * 2], bf[nt >> 1][(nt & 1) * 2 + 1]);
        }
        __syncthreads();
    }

    // ---------------- epilogue -----------------------------------------------
    const int g = lane >> 2, tg = lane & 3;
#pragma unroll
    for (int mt = 0; mt < 4; ++mt) {
#pragma unroll
        for (int nt = 0; nt < 4; ++nt) {
            const int m0 = bm + wm * 64 + mt * 16 + g;
            const int n0 = bn + wn * 32 + nt * 8 + tg * 2;
            float v0 = acc[mt][nt][0], v1 = acc[mt][nt][1];
            float v2 = acc[mt][nt][2], v3 = acc[mt][nt][3];
            if (BIAS) {
                float bb0 = bias[n0], bb1 = bias[n0 + 1];
                v0 += bb0; v1 += bb1; v2 += bb0; v3 += bb1;
            }
            v0 *= scale; v1 *= scale; v2 *= scale; v3 *= scale;
            if (RELU) {
                v0 = fmaxf(v0, 0.f); v1 = fmaxf(v1, 0.f);
                v2 = fmaxf(v2, 0.f); v3 = fmaxf(v3, 0.f);
            }
            if (OUT_BF16) {
                __nv_bfloat16* C = (__nv_bfloat16*)Cout;
                *(__nv_bfloat162*)(C + (size_t)m0 * N + n0)       = __floats2bfloat162_rn(v0, v1);
                *(__nv_bfloat162*)(C + (size_t)(m0 + 8) * N + n0) = __floats2bfloat162_rn(v2, v3);
            } else {
                float* C = (float*)Cout;
                *(float2*)(C + (size_t)m0 * N + n0)       = make_float2(v0, v1);
                *(float2*)(C + (size_t)(m0 + 8) * N + n0) = make_float2(v2, v3);
            }
        }
    }
}

// ======================= conversion / transpose ==============================
__global__ void cvt_bf16_kernel(const float* __restrict__ in,
                                __nv_bfloat16* __restrict__ out, int n4)
{
    int i = blockIdx.x * blockDim.x + threadIdx.x;
    if (i < n4) {
        float4 v = *(const float4*)(in + i * 4);
        __nv_bfloat162* o = (__nv_bfloat162*)(out + i * 4);
        o[0] = __floats2bfloat162_rn(v.x, v.y);
        o[1] = __floats2bfloat162_rn(v.z, v.w);
    }
}

// in: R x C fp32 row-major -> out: C x R bf16 row-major
__global__ void transpose_bf16_kernel(const float* __restrict__ in,
                                      __nv_bfloat16* __restrict__ out, int R, int C)
{
    __shared__ float tile[32][33];
    const int c0 = blockIdx.x * 32, r0 = blockIdx.y * 32;
    const int tx = threadIdx.x, ty = threadIdx.y;
#pragma unroll
    for (int i = ty; i < 32; i += 8)
        tile[i][tx] = in[(size_t)(r0 + i) * C + c0 + tx];
    __syncthreads();
#pragma unroll
    for (int i = ty; i < 32; i += 8)
        out[(size_t)(c0 + i) * R + r0 + tx] = __float2bfloat16(tile[tx][i]);
}

// ======================= normalize: fp32 in -> bf16 unit rows ================
__global__ void normalize_bf_kernel(const float* __restrict__ x,
                                    __nv_bfloat16* __restrict__ y)
{
    __shared__ float red[128];
    const int row = blockIdx.x, tid = threadIdx.x;
    const float* p = x + (size_t)row * PROJ;
    __nv_bfloat16* q = y + (size_t)row * PROJ;
    float s = 0.f;
    for (int j = tid; j < PROJ; j += 128) { float v = p[j]; s += v * v; }
    red[tid] = s; __syncthreads();
    for (int off = 64; off > 0; off >>= 1) {
        if (tid < off) red[tid] += red[tid + off];
        __syncthreads();
    }
    const float r = rsqrtf(red[0]);
    for (int j = tid; j < PROJ; j += 128) q[j] = __float2bfloat16(p[j] * r);
}

// ======================= mining + weighted CE ================================
__device__ __forceinline__ unsigned mono(float f)
{
    unsigned u = __float_as_uint(f);
    return (u & 0x80000000u) ? ~u : (u | 0x80000000u);
}

__global__ __launch_bounds__(256)
void mine_loss_kernel(const float* __restrict__ sim, const float* __restrict__ mw,
                      float* __restrict__ ce_out, int modal)
{
    __shared__ float    sh[B_SZ];
    __shared__ unsigned hist[256];
    __shared__ float    red[256];
    __shared__ unsigned s_prefix;
    __shared__ int      s_kth;

    const int row  = blockIdx.x;
    const int tid  = threadIdx.x;
    const int lane = tid & 31;
    const float* srow = sim + (size_t)row * B_SZ;

    for (int j = tid; j < B_SZ; j += 256) sh[j] = srow[j];
    __syncthreads();

    unsigned prefix = 0, pmask = 0;
    int kth = KSEL;
#pragma unroll
    for (int pass = 3; pass >= 0; --pass) {
        const int shift = pass * 8;
        hist[tid] = 0;
        __syncthreads();
        for (int j = tid; j < B_SZ; j += 256) {
            float s = sh[j];
            unsigned u = (j == row || s > 9.0f) ? 0u : mono(s);
            unsigned bin = ((u & pmask) == prefix) ? ((u >> shift) & 255u) : 0xFFFFFFFFu;
            unsigned peers = __match_any_sync(0xFFFFFFFFu, bin);
            if (bin != 0xFFFFFFFFu && lane == (unsigned)(__ffs(peers) - 1))
                atomicAdd(&hist[bin], (unsigned)__popc(peers));
        }
        __syncthreads();
        if (tid == 0) {
            int acc = 0, b = 255;
            for (;; --b) { acc += (int)hist[b]; if (acc >= kth || b == 0) break; }
            s_prefix = prefix | ((unsigned)b << shift);
            s_kth    = kth - (acc - (int)hist[b]);
        }
        __syncthreads();
        prefix = s_prefix; kth = s_kth;
        pmask |= (0xFFu << shift);
    }
    const unsigned thr = prefix;

    float vmax = -3.402823466e38f;
    for (int j = tid; j < B_SZ; j += 256) {
        float s = sh[j];
        bool diag  = (j == row);
        bool noise = (!diag) && (s > 9.0f);
        float w;
        if (noise)                        w = 0.5f;
        else if (!diag && mono(s) >= thr) w = 1.5f;
        else                              w = 1.0f;
        float v = s * w;
        sh[j] = v;
        vmax = fmaxf(vmax, v);
    }
    red[tid] = vmax; __syncthreads();
    for (int off = 128; off > 0; off >>= 1) {
        if (tid < off) red[tid] = fmaxf(red[tid], red[tid + off]);
        __syncthreads();
    }
    const float vm = red[0];
    __syncthreads();

    float ssum = 0.f;
    for (int j = tid; j < B_SZ; j += 256) ssum += expf(sh[j] - vm);
    red[tid] = ssum; __syncthreads();
    for (int off = 128; off > 0; off >>= 1) {
        if (tid < off) red[tid] += red[tid + off];
        __syncthreads();
    }
    if (tid == 0) {
        float lse = vm + logf(red[0]);
        float ce  = lse - sh[row];
        ce_out[modal * B_SZ + row] = ce * mw[(size_t)row * 2 + modal];
    }
}

__global__ void finalize_kernel(const float* __restrict__ ce, float* __restrict__ out)
{
    __shared__ float red[256];
    const int tid = threadIdx.x;
    float s = 0.f;
    for (int j = tid; j < 2 * B_SZ; j += 256) s += ce[j];
    red[tid] = s; __syncthreads();
    for (int off = 128; off > 0; off >>= 1) {
        if (tid < off) red[tid] += red[tid + off];
        __syncthreads();
    }
    if (tid == 0) out[0] = red[0] * (0.5f / (float)B_SZ);
}

// ======================= launch ==============================================
extern "C" void kernel_launch(void* const* d_in, const int* in_sizes, int n_in,
                              void* d_out, int out_size)
{
    const float* id_emb = (const float*)d_in[0];
    const float* text   = (const float*)d_in[1];
    const float* vis    = (const float*)d_in[2];
    const float* mw     = (const float*)d_in[3];
    const float* Wa_t = (const float*)d_in[4];  const float* ba_t = (const float*)d_in[5];
    const float* Wa_v = (const float*)d_in[6];  const float* ba_v = (const float*)d_in[7];
    const float* W1_t = (const float*)d_in[8];  const float* b1_t = (const float*)d_in[9];
    const float* W2_t = (const float*)d_in[10]; const float* b2_t = (const float*)d_in[11];
    const float* W1_v = (const float*)d_in[12]; const float* b1_v = (const float*)d_in[13];
    const float* W2_v = (const float*)d_in[14]; const float* b2_v = (const float*)d_in[15];

    __nv_bfloat16 *wa_t, *wa_v, *w1_t, *w1_v, *w2_t, *w2_v;
    __nv_bfloat16 *id_bf, *in_bf, *feat_bf, *h_bf, *mproj, *iproj;
    float *projf, *sim, *ce;
    cudaGetSymbolAddress((void**)&wa_t, g_Wa_t);   cudaGetSymbolAddress((void**)&wa_v, g_Wa_v);
    cudaGetSymbolAddress((void**)&w1_t, g_W1_t);   cudaGetSymbolAddress((void**)&w1_v, g_W1_v);
    cudaGetSymbolAddress((void**)&w2_t, g_W2_t);   cudaGetSymbolAddress((void**)&w2_v, g_W2_v);
    cudaGetSymbolAddress((void**)&id_bf, g_id_bf); cudaGetSymbolAddress((void**)&in_bf, g_in_bf);
    cudaGetSymbolAddress((void**)&feat_bf, g_feat_bf); cudaGetSymbolAddress((void**)&h_bf, g_h_bf);
    cudaGetSymbolAddress((void**)&projf, g_projf);
    cudaGetSymbolAddress((void**)&mproj, g_mproj); cudaGetSymbolAddress((void**)&iproj, g_iproj);
    cudaGetSymbolAddress((void**)&sim, g_sim);     cudaGetSymbolAddress((void**)&ce, g_ce);

    cudaFuncSetAttribute(hmma_gemm<false, true, true>,
                         cudaFuncAttributeMaxDynamicSharedMemorySize, TC_DSMEM);
    cudaFuncSetAttribute(hmma_gemm<true, true, true>,
                         cudaFuncAttributeMaxDynamicSharedMemorySize, TC_DSMEM);
    cudaFuncSetAttribute(hmma_gemm<false, true, false>,
                         cudaFuncAttributeMaxDynamicSharedMemorySize, TC_DSMEM);
    cudaFuncSetAttribute(hmma_gemm<false, false, false>,
                         cudaFuncAttributeMaxDynamicSharedMemorySize, TC_DSMEM);

    const dim3 tblk(32, 8);
    transpose_bf16_kernel<<<dim3(HID / 32, 768 / 32),  tblk>>>(Wa_t, wa_t, 768,  HID);
    transpose_bf16_kernel<<<dim3(HID / 32, 2048 / 32), tblk>>>(Wa_v, wa_v, 2048, HID);
    transpose_bf16_kernel<<<dim3(HID / 32, HID / 32),  tblk>>>(W1_t, w1_t, HID,  HID);
    transpose_bf16_kernel<<<dim3(HID / 32, HID / 32),  tblk>>>(W1_v, w1_v, HID,  HID);
    transpose_bf16_kernel<<<dim3(PROJ / 32, HID / 32), tblk>>>(W2_t, w2_t, HID,  PROJ);
    transpose_bf16_kernel<<<dim3(PROJ / 32, HID / 32), tblk>>>(W2_v, w2_v, HID,  PROJ);
    cvt_bf16_kernel<<<(B_SZ * HID / 4 + 255) / 256, 256>>>(id_emb, id_bf, B_SZ * HID / 4);

    struct Modal {
        const float* f; int kf;
        const __nv_bfloat16 *wa, *w1, *w2;
        const float *ba, *b1, *b2;
    };
    const Modal ms[2] = {
        { text,  768, wa_t, w1_t, w2_t, ba_t, b1_t, b2_t },   // modal 0 = text
        { vis,  2048, wa_v, w1_v, w2_v, ba_v, b1_v, b2_v },   // modal 1 = visual
    };

    for (int m = 0; m < 2; m++) {
        const int KF = ms[m].kf;
        cvt_bf16_kernel<<<(B_SZ * KF / 4 + 255) / 256, 256>>>(ms[m].f, in_bf, B_SZ * KF / 4);
        // adapter: feat = in @ Wa + ba (bf16 out)
        hmma_gemm<false, true, true><<<dim3(HID / 128, B_SZ / 128), 256, TC_DSMEM>>>(
            in_bf, ms[m].wa, ms[m].ba, feat_bf, B_SZ, HID, KF, 1.f);
        // modal projector
        hmma_gemm<true, true, true><<<dim3(HID / 128, B_SZ / 128), 256, TC_DSMEM>>>(
            feat_bf, ms[m].w1, ms[m].b1, h_bf, B_SZ, HID, HID, 1.f);
        hmma_gemm<false, true, false><<<dim3(PROJ / 128, B_SZ / 128), 256, TC_DSMEM>>>(
            h_bf, ms[m].w2, ms[m].b2, projf, B_SZ, PROJ, HID, 1.f);
        normalize_bf_kernel<<<B_SZ, 128>>>(projf, mproj);
        // id projector
        hmma_gemm<true, true, true><<<dim3(HID / 128, B_SZ / 128), 256, TC_DSMEM>>>(
            id_bf, ms[m].w1, ms[m].b1, h_bf, B_SZ, HID, HID, 1.f);
        hmma_gemm<false, true, false><<<dim3(PROJ / 128, B_SZ / 128), 256, TC_DSMEM>>>(
            h_bf, ms[m].w2, ms[m].b2, projf, B_SZ, PROJ, HID, 1.f);
        normalize_bf_kernel<<<B_SZ, 128>>>(projf, iproj);
        // sim = (iproj @ mproj^T) * 10
        hmma_gemm<false, false, false><<<dim3(B_SZ / 128, B_SZ / 128), 256, TC_DSMEM>>>(
            iproj, mproj, nullptr, sim, B_SZ, B_SZ, PROJ, 10.0f);
        mine_loss_kernel<<<B_SZ, 256>>>(sim, mw, ce, m);
    }
    finalize_kernel<<<1, 256>>>(ce, (float*)d_out);
}

// round 5
// speedup vs baseline: 3.4302x; 1.0187x over previous
#include <cuda_runtime.h>
#include <cuda_bf16.h>
#include <cstdint>

#define B_SZ 8192
#define HID  1024
#define PROJ 512
#define KSEL 4096

// ======================= helpers =============================================
__device__ __forceinline__ uint32_t smem_to_u32(const void* p) {
    uint32_t a;
    asm("{ .reg .u64 t; cvta.to.shared.u64 t, %1; cvt.u32.u64 %0, t; }"
        : "=r"(a) : "l"(p));
    return a;
}
#define SW128(off) ((off) ^ (((off) >> 3) & 0x70))

__device__ __forceinline__ void cp_async16(uint32_t dst, const void* src) {
    asm volatile("cp.async.cg.shared.global [%0], [%1], 16;"
                 :: "r"(dst), "l"(src) : "memory");
}
__device__ __forceinline__ void ldsm_x4(uint32_t& r0, uint32_t& r1,
                                        uint32_t& r2, uint32_t& r3, uint32_t addr) {
    asm volatile("ldmatrix.sync.aligned.m8n8.x4.shared.b16 {%0,%1,%2,%3}, [%4];"
                 : "=r"(r0), "=r"(r1), "=r"(r2), "=r"(r3) : "r"(addr));
}
__device__ __forceinline__ void mma_bf16(float* c, const uint32_t* a,
                                         uint32_t b0, uint32_t b1) {
    asm volatile(
        "mma.sync.aligned.m16n8k16.row.col.f32.bf16.bf16.f32 "
        "{%0,%1,%2,%3}, {%4,%5,%6,%7}, {%8,%9}, {%0,%1,%2,%3};"
        : "+f"(c[0]), "+f"(c[1]), "+f"(c[2]), "+f"(c[3])
        : "r"(a[0]), "r"(a[1]), "r"(a[2]), "r"(a[3]), "r"(b0), "r"(b1));
}

// ======================= scratch (device globals) ============================
__device__ __align__(16) __nv_bfloat16 g_Wa_t[HID * 768];
__device__ __align__(16) __nv_bfloat16 g_Wa_v[HID * 2048];
__device__ __align__(16) __nv_bfloat16 g_W1_t[HID * HID];
__device__ __align__(16) __nv_bfloat16 g_W1_v[HID * HID];
__device__ __align__(16) __nv_bfloat16 g_W2_t[PROJ * HID];
__device__ __align__(16) __nv_bfloat16 g_W2_v[PROJ * HID];
__device__ __align__(16) __nv_bfloat16 g_id_bf[B_SZ * HID];
__device__ __align__(16) __nv_bfloat16 g_in_bf[B_SZ * 2048];
__device__ __align__(16) __nv_bfloat16 g_feat_bf[B_SZ * HID];
__device__ __align__(16) __nv_bfloat16 g_h_bf[B_SZ * HID];
__device__ __align__(16) float         g_projf[B_SZ * PROJ];
__device__ __align__(16) __nv_bfloat16 g_mproj[B_SZ * PROJ];
__device__ __align__(16) __nv_bfloat16 g_iproj[B_SZ * PROJ];
__device__ float g_sim[(size_t)B_SZ * B_SZ];
__device__ float g_ce[2 * B_SZ];

// ======================= HMMA GEMM ===========================================
// C[M,N] = epi(A[M,K] @ Bw[N,K]^T). bf16 in, fp32 accum.
// CTA tile 128x128, 8 warps of 64x32, K-tile 64 (bf16).
// 3-stage cp.async pipeline + k16 fragment double-buffering.
static constexpr int STAGES   = 3;
static constexpr int TC_DSMEM = STAGES * 32 * 1024 + 1024;

template <bool RELU, bool BIAS, bool OUT_BF16>
__global__ __launch_bounds__(256)
void hmma_gemm(const __nv_bfloat16* __restrict__ A, const __nv_bfloat16* __restrict__ Bw,
               const float* __restrict__ bias, void* __restrict__ Cout,
               int M, int N, int K, float scale)
{
    extern __shared__ char dsm[];
    const uint32_t base_u  = smem_to_u32(dsm);
    const uint32_t tiles_u = (base_u + 1023u) & ~1023u;

    const int tid  = threadIdx.x;
    const int wid  = tid >> 5, lane = tid & 31;
    const int wm   = wid >> 2, wn = wid & 3;          // 2 x 4 warp grid
    const int bm   = blockIdx.y * 128, bn = blockIdx.x * 128;
    const int nsteps = K >> 6;

    float acc[4][4][4];
#pragma unroll
    for (int i = 0; i < 4; i++)
#pragma unroll
        for (int j = 0; j < 4; j++)
#pragma unroll
            for (int r = 0; r < 4; r++) acc[i][j][r] = 0.f;

    // loader: 32 base rows x 8 chunks, h strides rows by 32 -> full 16KB per tile.
    const int lr = tid >> 3;
    const int lc = tid & 7;

    auto load_stage = [&](int buf, int k0) {
        const uint32_t tA = tiles_u + (uint32_t)buf * 32768u;
        const uint32_t tB = tA + 16384u;
#pragma unroll
        for (int h = 0; h < 4; h++) {
            int r = lr + h * 32;
            uint32_t sw = SW128((uint32_t)(r * 128 + lc * 16));
            cp_async16(tA + sw, A  + (size_t)(bm + r) * K + k0 + lc * 8);
            cp_async16(tB + sw, Bw + (size_t)(bn + r) * K + k0 + lc * 8);
        }
    };

    // ldmatrix fragment fetch for one k16 slice of the resident stage
    const int a_row  = wm * 64 + (lane & 15);
    const int a_colb = (lane >> 4) << 4;
    const int b_row0 = wn * 32 + (lane & 7) + ((lane >> 4) << 3);
    const int b_colb = ((lane >> 3) & 1) << 4;

    auto ld_frags = [&](uint32_t tA, uint32_t tB, int kk,
                        uint32_t a[4][4], uint32_t bf[2][4]) {
        const int kb = kk * 32;
#pragma unroll
        for (int mt = 0; mt < 4; ++mt)
            ldsm_x4(a[mt][0], a[mt][1], a[mt][2], a[mt][3],
                    tA + SW128((uint32_t)((a_row + mt * 16) * 128 + kb + a_colb)));
#pragma unroll
        for (int np = 0; np < 2; ++np)
            ldsm_x4(bf[np][0], bf[np][1], bf[np][2], bf[np][3],
                    tB + SW128((uint32_t)((b_row0 + np * 16) * 128 + kb + b_colb)));
    };

    // prologue: fill first two stages
    load_stage(0, 0);
    asm volatile("cp.async.commit_group;" ::: "memory");
    if (nsteps > 1) load_stage(1, 64);
    asm volatile("cp.async.commit_group;" ::: "memory");

    uint32_t afr[2][4][4], bfr[2][2][4];

    for (int s = 0; s < nsteps; ++s) {
        // stage s ready once only the newest committed group may be pending
        asm volatile("cp.async.wait_group 1;" ::: "memory");
        __syncthreads();

        // start loading stage s+2 (overwrites buffer consumed at stage s-1)
        if (s + 2 < nsteps) load_stage((s + 2) % STAGES, (s + 2) << 6);
        asm volatile("cp.async.commit_group;" ::: "memory");

        const uint32_t tA = tiles_u + (uint32_t)(s % STAGES) * 32768u;
        const uint32_t tB = tA + 16384u;

        ld_frags(tA, tB, 0, afr[0], bfr[0]);
#pragma unroll
        for (int kk = 0; kk < 4; ++kk) {
            const int cur = kk & 1;
            if (kk < 3) ld_frags(tA, tB, kk + 1, afr[cur ^ 1], bfr[cur ^ 1]);
#pragma unroll
            for (int mt = 0; mt < 4; ++mt)
#pragma unroll
                for (int nt = 0; nt < 4; ++nt)
                    mma_bf16(acc[mt][nt], afr[cur][mt],
                             bfr[cur][nt >> 1][(nt & 1) * 2],
                             bfr[cur][nt >> 1][(nt & 1) * 2 + 1]);
        }
        __syncthreads();
    }

    // ---------------- epilogue -----------------------------------------------
    const int g = lane >> 2, tg = lane & 3;
#pragma unroll
    for (int mt = 0; mt < 4; ++mt) {
#pragma unroll
        for (int nt = 0; nt < 4; ++nt) {
            const int m0 = bm + wm * 64 + mt * 16 + g;
            const int n0 = bn + wn * 32 + nt * 8 + tg * 2;
            float v0 = acc[mt][nt][0], v1 = acc[mt][nt][1];
            float v2 = acc[mt][nt][2], v3 = acc[mt][nt][3];
            if (BIAS) {
                float bb0 = bias[n0], bb1 = bias[n0 + 1];
                v0 += bb0; v1 += bb1; v2 += bb0; v3 += bb1;
            }
            v0 *= scale; v1 *= scale; v2 *= scale; v3 *= scale;
            if (RELU) {
                v0 = fmaxf(v0, 0.f); v1 = fmaxf(v1, 0.f);
                v2 = fmaxf(v2, 0.f); v3 = fmaxf(v3, 0.f);
            }
            if (OUT_BF16) {
                __nv_bfloat16* C = (__nv_bfloat16*)Cout;
                *(__nv_bfloat162*)(C + (size_t)m0 * N + n0)       = __floats2bfloat162_rn(v0, v1);
                *(__nv_bfloat162*)(C + (size_t)(m0 + 8) * N + n0) = __floats2bfloat162_rn(v2, v3);
            } else {
                float* C = (float*)Cout;
                *(float2*)(C + (size_t)m0 * N + n0)       = make_float2(v0, v1);
                *(float2*)(C + (size_t)(m0 + 8) * N + n0) = make_float2(v2, v3);
            }
        }
    }
}

// ======================= conversion / transpose ==============================
__global__ void cvt_bf16_kernel(const float* __restrict__ in,
                                __nv_bfloat16* __restrict__ out, int n4)
{
    int i = blockIdx.x * blockDim.x + threadIdx.x;
    if (i < n4) {
        float4 v = *(const float4*)(in + i * 4);
        __nv_bfloat162* o = (__nv_bfloat162*)(out + i * 4);
        o[0] = __floats2bfloat162_rn(v.x, v.y);
        o[1] = __floats2bfloat162_rn(v.z, v.w);
    }
}

// in: R x C fp32 row-major -> out: C x R bf16 row-major
__global__ void transpose_bf16_kernel(const float* __restrict__ in,
                                      __nv_bfloat16* __restrict__ out, int R, int C)
{
    __shared__ float tile[32][33];
    const int c0 = blockIdx.x * 32, r0 = blockIdx.y * 32;
    const int tx = threadIdx.x, ty = threadIdx.y;
#pragma unroll
    for (int i = ty; i < 32; i += 8)
        tile[i][tx] = in[(size_t)(r0 + i) * C + c0 + tx];
    __syncthreads();
#pragma unroll
    for (int i = ty; i < 32; i += 8)
        out[(size_t)(c0 + i) * R + r0 + tx] = __float2bfloat16(tile[tx][i]);
}

// ======================= normalize: fp32 in -> bf16 unit rows ================
__global__ void normalize_bf_kernel(const float* __restrict__ x,
                                    __nv_bfloat16* __restrict__ y)
{
    __shared__ float red[128];
    const int row = blockIdx.x, tid = threadIdx.x;
    const float* p = x + (size_t)row * PROJ;
    __nv_bfloat16* q = y + (size_t)row * PROJ;
    float s = 0.f;
    for (int j = tid; j < PROJ; j += 128) { float v = p[j]; s += v * v; }
    red[tid] = s; __syncthreads();
    for (int off = 64; off > 0; off >>= 1) {
        if (tid < off) red[tid] += red[tid + off];
        __syncthreads();
    }
    const float r = rsqrtf(red[0]);
    for (int j = tid; j < PROJ; j += 128) q[j] = __float2bfloat16(p[j] * r);
}

// ======================= mining + weighted CE ================================
__device__ __forceinline__ unsigned mono(float f)
{
    unsigned u = __float_as_uint(f);
    return (u & 0x80000000u) ? ~u : (u | 0x80000000u);
}

__global__ __launch_bounds__(256)
void mine_loss_kernel(const float* __restrict__ sim, const float* __restrict__ mw,
                      float* __restrict__ ce_out, int modal)
{
    __shared__ float    sh[B_SZ];
    __shared__ unsigned hist[256];
    __shared__ float    red[256];
    __shared__ unsigned s_prefix;
    __shared__ int      s_kth;

    const int row  = blockIdx.x;
    const int tid  = threadIdx.x;
    const int lane = tid & 31;
    const float* srow = sim + (size_t)row * B_SZ;

    for (int j = tid; j < B_SZ; j += 256) sh[j] = srow[j];
    __syncthreads();

    unsigned prefix = 0, pmask = 0;
    int kth = KSEL;
#pragma unroll
    for (int pass = 3; pass >= 0; --pass) {
        const int shift = pass * 8;
        hist[tid] = 0;
        __syncthreads();
        for (int j = tid; j < B_SZ; j += 256) {
            float s = sh[j];
            unsigned u = (j == row || s > 9.0f) ? 0u : mono(s);
            unsigned bin = ((u & pmask) == prefix) ? ((u >> shift) & 255u) : 0xFFFFFFFFu;
            unsigned peers = __match_any_sync(0xFFFFFFFFu, bin);
            if (bin != 0xFFFFFFFFu && lane == (unsigned)(__ffs(peers) - 1))
                atomicAdd(&hist[bin], (unsigned)__popc(peers));
        }
        __syncthreads();
        if (tid == 0) {
            int acc = 0, b = 255;
            for (;; --b) { acc += (int)hist[b]; if (acc >= kth || b == 0) break; }
            s_prefix = prefix | ((unsigned)b << shift);
            s_kth    = kth - (acc - (int)hist[b]);
        }
        __syncthreads();
        prefix = s_prefix; kth = s_kth;
        pmask |= (0xFFu << shift);
    }
    const unsigned thr = prefix;

    float vmax = -3.402823466e38f;
    for (int j = tid; j < B_SZ; j += 256) {
        float s = sh[j];
        bool diag  = (j == row);
        bool noise = (!diag) && (s > 9.0f);
        float w;
        if (noise)                        w = 0.5f;
        else if (!diag && mono(s) >= thr) w = 1.5f;
        else                              w = 1.0f;
        float v = s * w;
        sh[j] = v;
        vmax = fmaxf(vmax, v);
    }
    red[tid] = vmax; __syncthreads();
    for (int off = 128; off > 0; off >>= 1) {
        if (tid < off) red[tid] = fmaxf(red[tid], red[tid + off]);
        __syncthreads();
    }
    const float vm = red[0];
    __syncthreads();

    float ssum = 0.f;
    for (int j = tid; j < B_SZ; j += 256) ssum += expf(sh[j] - vm);
    red[tid] = ssum; __syncthreads();
    for (int off = 128; off > 0; off >>= 1) {
        if (tid < off) red[tid] += red[tid + off];
        __syncthreads();
    }
    if (tid == 0) {
        float lse = vm + logf(red[0]);
        float ce  = lse - sh[row];
        ce_out[modal * B_SZ + row] = ce * mw[(size_t)row * 2 + modal];
    }
}

__global__ void finalize_kernel(const float* __restrict__ ce, float* __restrict__ out)
{
    __shared__ float red[256];
    const int tid = threadIdx.x;
    float s = 0.f;
    for (int j = tid; j < 2 * B_SZ; j += 256) s += ce[j];
    red[tid] = s; __syncthreads();
    for (int off = 128; off > 0; off >>= 1) {
        if (tid < off) red[tid] += red[tid + off];
        __syncthreads();
    }
    if (tid == 0) out[0] = red[0] * (0.5f / (float)B_SZ);
}

// ======================= launch ==============================================
extern "C" void kernel_launch(void* const* d_in, const int* in_sizes, int n_in,
                              void* d_out, int out_size)
{
    const float* id_emb = (const float*)d_in[0];
    const float* text   = (const float*)d_in[1];
    const float* vis    = (const float*)d_in[2];
    const float* mw     = (const float*)d_in[3];
    const float* Wa_t = (const float*)d_in[4];  const float* ba_t = (const float*)d_in[5];
    const float* Wa_v = (const float*)d_in[6];  const float* ba_v = (const float*)d_in[7];
    const float* W1_t = (const float*)d_in[8];  const float* b1_t = (const float*)d_in[9];
    const float* W2_t = (const float*)d_in[10]; const float* b2_t = (const float*)d_in[11];
    const float* W1_v = (const float*)d_in[12]; const float* b1_v = (const float*)d_in[13];
    const float* W2_v = (const float*)d_in[14]; const float* b2_v = (const float*)d_in[15];

    __nv_bfloat16 *wa_t, *wa_v, *w1_t, *w1_v, *w2_t, *w2_v;
    __nv_bfloat16 *id_bf, *in_bf, *feat_bf, *h_bf, *mproj, *iproj;
    float *projf, *sim, *ce;
    cudaGetSymbolAddress((void**)&wa_t, g_Wa_t);   cudaGetSymbolAddress((void**)&wa_v, g_Wa_v);
    cudaGetSymbolAddress((void**)&w1_t, g_W1_t);   cudaGetSymbolAddress((void**)&w1_v, g_W1_v);
    cudaGetSymbolAddress((void**)&w2_t, g_W2_t);   cudaGetSymbolAddress((void**)&w2_v, g_W2_v);
    cudaGetSymbolAddress((void**)&id_bf, g_id_bf); cudaGetSymbolAddress((void**)&in_bf, g_in_bf);
    cudaGetSymbolAddress((void**)&feat_bf, g_feat_bf); cudaGetSymbolAddress((void**)&h_bf, g_h_bf);
    cudaGetSymbolAddress((void**)&projf, g_projf);
    cudaGetSymbolAddress((void**)&mproj, g_mproj); cudaGetSymbolAddress((void**)&iproj, g_iproj);
    cudaGetSymbolAddress((void**)&sim, g_sim);     cudaGetSymbolAddress((void**)&ce, g_ce);

    cudaFuncSetAttribute(hmma_gemm<false, true, true>,
                         cudaFuncAttributeMaxDynamicSharedMemorySize, TC_DSMEM);
    cudaFuncSetAttribute(hmma_gemm<true, true, true>,
                         cudaFuncAttributeMaxDynamicSharedMemorySize, TC_DSMEM);
    cudaFuncSetAttribute(hmma_gemm<false, true, false>,
                         cudaFuncAttributeMaxDynamicSharedMemorySize, TC_DSMEM);
    cudaFuncSetAttribute(hmma_gemm<false, false, false>,
                         cudaFuncAttributeMaxDynamicSharedMemorySize, TC_DSMEM);

    const dim3 tblk(32, 8);
    transpose_bf16_kernel<<<dim3(HID / 32, 768 / 32),  tblk>>>(Wa_t, wa_t, 768,  HID);
    transpose_bf16_kernel<<<dim3(HID / 32, 2048 / 32), tblk>>>(Wa_v, wa_v, 2048, HID);
    transpose_bf16_kernel<<<dim3(HID / 32, HID / 32),  tblk>>>(W1_t, w1_t, HID,  HID);
    transpose_bf16_kernel<<<dim3(HID / 32, HID / 32),  tblk>>>(W1_v, w1_v, HID,  HID);
    transpose_bf16_kernel<<<dim3(PROJ / 32, HID / 32), tblk>>>(W2_t, w2_t, HID,  PROJ);
    transpose_bf16_kernel<<<dim3(PROJ / 32, HID / 32), tblk>>>(W2_v, w2_v, HID,  PROJ);
    cvt_bf16_kernel<<<(B_SZ * HID / 4 + 255) / 256, 256>>>(id_emb, id_bf, B_SZ * HID / 4);

    struct Modal {
        const float* f; int kf;
        const __nv_bfloat16 *wa, *w1, *w2;
        const float *ba, *b1, *b2;
    };
    const Modal ms[2] = {
        { text,  768, wa_t, w1_t, w2_t, ba_t, b1_t, b2_t },   // modal 0 = text
        { vis,  2048, wa_v, w1_v, w2_v, ba_v, b1_v, b2_v },   // modal 1 = visual
    };

    for (int m = 0; m < 2; m++) {
        const int KF = ms[m].kf;
        cvt_bf16_kernel<<<(B_SZ * KF / 4 + 255) / 256, 256>>>(ms[m].f, in_bf, B_SZ * KF / 4);
        // adapter: feat = in @ Wa + ba (bf16 out)
        hmma_gemm<false, true, true><<<dim3(HID / 128, B_SZ / 128), 256, TC_DSMEM>>>(
            in_bf, ms[m].wa, ms[m].ba, feat_bf, B_SZ, HID, KF, 1.f);
        // modal projector
        hmma_gemm<true, true, true><<<dim3(HID / 128, B_SZ / 128), 256, TC_DSMEM>>>(
            feat_bf, ms[m].w1, ms[m].b1, h_bf, B_SZ, HID, HID, 1.f);
        hmma_gemm<false, true, false><<<dim3(PROJ / 128, B_SZ / 128), 256, TC_DSMEM>>>(
            h_bf, ms[m].w2, ms[m].b2, projf, B_SZ, PROJ, HID, 1.f);
        normalize_bf_kernel<<<B_SZ, 128>>>(projf, mproj);
        // id projector
        hmma_gemm<true, true, true><<<dim3(HID / 128, B_SZ / 128), 256, TC_DSMEM>>>(
            id_bf, ms[m].w1, ms[m].b1, h_bf, B_SZ, HID, HID, 1.f);
        hmma_gemm<false, true, false><<<dim3(PROJ / 128, B_SZ / 128), 256, TC_DSMEM>>>(
            h_bf, ms[m].w2, ms[m].b2, projf, B_SZ, PROJ, HID, 1.f);
        normalize_bf_kernel<<<B_SZ, 128>>>(projf, iproj);
        // sim = (iproj @ mproj^T) * 10
        hmma_gemm<false, false, false><<<dim3(B_SZ / 128, B_SZ / 128), 256, TC_DSMEM>>>(
            iproj, mproj, nullptr, sim, B_SZ, B_SZ, PROJ, 10.0f);
        mine_loss_kernel<<<B_SZ, 256>>>(sim, mw, ce, m);
    }
    finalize_kernel<<<1, 256>>>(ce, (float*)d_out);
}

// round 7
// speedup vs baseline: 3.4397x; 1.0028x over previous
#include <cuda_runtime.h>
#include <cuda_bf16.h>
#include <cstdint>

#define B_SZ 8192
#define HID  1024
#define PROJ 512
#define KSEL 4096

// ======================= helpers =============================================
__device__ __forceinline__ uint32_t smem_to_u32(const void* p) {
    uint32_t a;
    asm("{ .reg .u64 t; cvta.to.shared.u64 t, %1; cvt.u32.u64 %0, t; }"
        : "=r"(a) : "l"(p));
    return a;
}
#define SW128(off) ((off) ^ (((off) >> 3) & 0x70))

__device__ __forceinline__ void cp_async16(uint32_t dst, const void* src) {
    asm volatile("cp.async.cg.shared.global [%0], [%1], 16;"
                 :: "r"(dst), "l"(src) : "memory");
}
__device__ __forceinline__ void ldsm_x4(uint32_t& r0, uint32_t& r1,
                                        uint32_t& r2, uint32_t& r3, uint32_t addr) {
    asm volatile("ldmatrix.sync.aligned.m8n8.x4.shared.b16 {%0,%1,%2,%3}, [%4];"
                 : "=r"(r0), "=r"(r1), "=r"(r2), "=r"(r3) : "r"(addr));
}
__device__ __forceinline__ void mma_bf16(float* c, const uint32_t* a,
                                         uint32_t b0, uint32_t b1) {
    asm volatile(
        "mma.sync.aligned.m16n8k16.row.col.f32.bf16.bf16.f32 "
        "{%0,%1,%2,%3}, {%4,%5,%6,%7}, {%8,%9}, {%0,%1,%2,%3};"
        : "+f"(c[0]), "+f"(c[1]), "+f"(c[2]), "+f"(c[3])
        : "r"(a[0]), "r"(a[1]), "r"(a[2]), "r"(a[3]), "r"(b0), "r"(b1));
}

// ======================= scratch (device globals) ============================
__device__ __align__(16) __nv_bfloat16 g_Wa_t[HID * 768];
__device__ __align__(16) __nv_bfloat16 g_Wa_v[HID * 2048];
__device__ __align__(16) __nv_bfloat16 g_W1_t[HID * HID];
__device__ __align__(16) __nv_bfloat16 g_W1_v[HID * HID];
__device__ __align__(16) __nv_bfloat16 g_W2_t[PROJ * HID];
__device__ __align__(16) __nv_bfloat16 g_W2_v[PROJ * HID];
__device__ __align__(16) __nv_bfloat16 g_id_bf[B_SZ * HID];
__device__ __align__(16) __nv_bfloat16 g_in_bf[B_SZ * 2048];
__device__ __align__(16) __nv_bfloat16 g_feat_bf[B_SZ * HID];
__device__ __align__(16) __nv_bfloat16 g_h_bf[B_SZ * HID];
__device__ __align__(16) float         g_projf[B_SZ * PROJ];
__device__ __align__(16) __nv_bfloat16 g_mproj[B_SZ * PROJ];
__device__ __align__(16) __nv_bfloat16 g_iproj[B_SZ * PROJ];
__device__ float g_sim[(size_t)B_SZ * B_SZ];
__device__ float g_ce[2 * B_SZ];

// ======================= HMMA GEMM (128x128 CTA tile) ========================
static constexpr int STAGES   = 3;
static constexpr int TC_DSMEM = STAGES * 32 * 1024 + 1024;

template <bool RELU, bool BIAS, bool OUT_BF16>
__global__ __launch_bounds__(256)
void hmma_gemm(const __nv_bfloat16* __restrict__ A, const __nv_bfloat16* __restrict__ Bw,
               const float* __restrict__ bias, void* __restrict__ Cout,
               int M, int N, int K, float scale)
{
    extern __shared__ char dsm[];
    const uint32_t base_u  = smem_to_u32(dsm);
    const uint32_t tiles_u = (base_u + 1023u) & ~1023u;

    const int tid  = threadIdx.x;
    const int wid  = tid >> 5, lane = tid & 31;
    const int wm   = wid >> 2, wn = wid & 3;          // 2 x 4 warp grid
    const int bm   = blockIdx.y * 128, bn = blockIdx.x * 128;
    const int nsteps = K >> 6;

    float acc[4][4][4];
#pragma unroll
    for (int i = 0; i < 4; i++)
#pragma unroll
        for (int j = 0; j < 4; j++)
#pragma unroll
            for (int r = 0; r < 4; r++) acc[i][j][r] = 0.f;

    const int lr = tid >> 3;
    const int lc = tid & 7;

    auto load_stage = [&](int buf, int k0) {
        const uint32_t tA = tiles_u + (uint32_t)buf * 32768u;
        const uint32_t tB = tA + 16384u;
#pragma unroll
        for (int h = 0; h < 4; h++) {
            int r = lr + h * 32;
            uint32_t sw = SW128((uint32_t)(r * 128 + lc * 16));
            cp_async16(tA + sw, A  + (size_t)(bm + r) * K + k0 + lc * 8);
            cp_async16(tB + sw, Bw + (size_t)(bn + r) * K + k0 + lc * 8);
        }
    };

    const int a_row  = wm * 64 + (lane & 15);
    const int a_colb = (lane >> 4) << 4;
    const int b_row0 = wn * 32 + (lane & 7) + ((lane >> 4) << 3);
    const int b_colb = ((lane >> 3) & 1) << 4;

    auto ld_frags = [&](uint32_t tA, uint32_t tB, int kk,
                        uint32_t a[4][4], uint32_t bf[2][4]) {
        const int kb = kk * 32;
#pragma unroll
        for (int mt = 0; mt < 4; ++mt)
            ldsm_x4(a[mt][0], a[mt][1], a[mt][2], a[mt][3],
                    tA + SW128((uint32_t)((a_row + mt * 16) * 128 + kb + a_colb)));
#pragma unroll
        for (int np = 0; np < 2; ++np)
            ldsm_x4(bf[np][0], bf[np][1], bf[np][2], bf[np][3],
                    tB + SW128((uint32_t)((b_row0 + np * 16) * 128 + kb + b_colb)));
    };

    load_stage(0, 0);
    asm volatile("cp.async.commit_group;" ::: "memory");
    if (nsteps > 1) load_stage(1, 64);
    asm volatile("cp.async.commit_group;" ::: "memory");

    uint32_t afr[2][4][4], bfr[2][2][4];

    for (int s = 0; s < nsteps; ++s) {
        asm volatile("cp.async.wait_group 1;" ::: "memory");
        __syncthreads();

        if (s + 2 < nsteps) load_stage((s + 2) % STAGES, (s + 2) << 6);
        asm volatile("cp.async.commit_group;" ::: "memory");

        const uint32_t tA = tiles_u + (uint32_t)(s % STAGES) * 32768u;
        const uint32_t tB = tA + 16384u;

        ld_frags(tA, tB, 0, afr[0], bfr[0]);
#pragma unroll
        for (int kk = 0; kk < 4; ++kk) {
            const int cur = kk & 1;
            if (kk < 3) ld_frags(tA, tB, kk + 1, afr[cur ^ 1], bfr[cur ^ 1]);
#pragma unroll
            for (int mt = 0; mt < 4; ++mt)
#pragma unroll
                for (int nt = 0; nt < 4; ++nt)
                    mma_bf16(acc[mt][nt], afr[cur][mt],
                             bfr[cur][nt >> 1][(nt & 1) * 2],
                             bfr[cur][nt >> 1][(nt & 1) * 2 + 1]);
        }
        __syncthreads();
    }

    const int g = lane >> 2, tg = lane & 3;
#pragma unroll
    for (int mt = 0; mt < 4; ++mt) {
#pragma unroll
        for (int nt = 0; nt < 4; ++nt) {
            const int m0 = bm + wm * 64 + mt * 16 + g;
            const int n0 = bn + wn * 32 + nt * 8 + tg * 2;
            float v0 = acc[mt][nt][0], v1 = acc[mt][nt][1];
            float v2 = acc[mt][nt][2], v3 = acc[mt][nt][3];
            if (BIAS) {
                float bb0 = bias[n0], bb1 = bias[n0 + 1];
                v0 += bb0; v1 += bb1; v2 += bb0; v3 += bb1;
            }
            v0 *= scale; v1 *= scale; v2 *= scale; v3 *= scale;
            if (RELU) {
                v0 = fmaxf(v0, 0.f); v1 = fmaxf(v1, 0.f);
                v2 = fmaxf(v2, 0.f); v3 = fmaxf(v3, 0.f);
            }
            if (OUT_BF16) {
                __nv_bfloat16* C = (__nv_bfloat16*)Cout;
                *(__nv_bfloat162*)(C + (size_t)m0 * N + n0)       = __floats2bfloat162_rn(v0, v1);
                *(__nv_bfloat162*)(C + (size_t)(m0 + 8) * N + n0) = __floats2bfloat162_rn(v2, v3);
            } else {
                float* C = (float*)Cout;
                *(float2*)(C + (size_t)m0 * N + n0)       = make_float2(v0, v1);
                *(float2*)(C + (size_t)(m0 + 8) * N + n0) = make_float2(v2, v3);
            }
        }
    }
}

// ======================= HMMA GEMM (128x256 CTA tile, sim only) ==============
static constexpr int ST256        = 3;
static constexpr int STAGE_BYTES  = 48 * 1024;
static constexpr int TC_DSMEM_256 = ST256 * STAGE_BYTES + 1024;

__global__ __launch_bounds__(256, 1)
void hmma_gemm_256(const __nv_bfloat16* __restrict__ A, const __nv_bfloat16* __restrict__ Bw,
                   float* __restrict__ Cout, int M, int N, int K, float scale)
{
    extern __shared__ char dsm[];
    const uint32_t base_u  = smem_to_u32(dsm);
    const uint32_t tiles_u = (base_u + 1023u) & ~1023u;

    const int tid  = threadIdx.x;
    const int wid  = tid >> 5, lane = tid & 31;
    const int wm   = wid >> 2, wn = wid & 3;          // 2 x 4 warp grid (64x64 tiles)
    const int bm   = blockIdx.y * 128, bn = blockIdx.x * 256;
    const int nsteps = K >> 6;

    float acc[4][8][4];
#pragma unroll
    for (int i = 0; i < 4; i++)
#pragma unroll
        for (int j = 0; j < 8; j++)
#pragma unroll
            for (int r = 0; r < 4; r++) acc[i][j][r] = 0.f;

    const int lr = tid >> 3;
    const int lc = tid & 7;

    auto load_stage = [&](int buf, int k0) {
        const uint32_t tA = tiles_u + (uint32_t)buf * (uint32_t)STAGE_BYTES;
        const uint32_t tB = tA + 16384u;
#pragma unroll
        for (int h = 0; h < 4; h++) {
            int r = lr + h * 32;
            uint32_t sw = SW128((uint32_t)(r * 128 + lc * 16));
            cp_async16(tA + sw, A + (size_t)(bm + r) * K + k0 + lc * 8);
        }
#pragma unroll
        for (int h = 0; h < 8; h++) {
            int r = lr + h * 32;
            uint32_t sw = SW128((uint32_t)(r * 128 + lc * 16));
            cp_async16(tB + sw, Bw + (size_t)(bn + r) * K + k0 + lc * 8);
        }
        asm volatile("cp.async.commit_group;" ::: "memory");
    };

    const int a_row  = wm * 64 + (lane & 15);
    const int a_colb = (lane >> 4) << 4;
    const int b_row0 = wn * 64 + (lane & 7) + ((lane >> 4) << 3);
    const int b_colb = ((lane >> 3) & 1) << 4;

    load_stage(0, 0);
    if (nsteps > 1) load_stage(1, 64);

    for (int s = 0; s < nsteps; ++s) {
        asm volatile("cp.async.wait_group 1;" ::: "memory");
        __syncthreads();

        if (s + 2 < nsteps) load_stage((s + 2) % ST256, (s + 2) << 6);
        else                asm volatile("cp.async.commit_group;" ::: "memory");

        const uint32_t tA = tiles_u + (uint32_t)(s % ST256) * (uint32_t)STAGE_BYTES;
        const uint32_t tB = tA + 16384u;

#pragma unroll
        for (int kk = 0; kk < 4; ++kk) {
            const int kb = kk * 32;
            uint32_t afr[4][4];
#pragma unroll
            for (int mt = 0; mt < 4; ++mt)
                ldsm_x4(afr[mt][0], afr[mt][1], afr[mt][2], afr[mt][3],
                        tA + SW128((uint32_t)((a_row + mt * 16) * 128 + kb + a_colb)));
            uint32_t bfr[4][4];
#pragma unroll
            for (int np = 0; np < 4; ++np)
                ldsm_x4(bfr[np][0], bfr[np][1], bfr[np][2], bfr[np][3],
                        tB + SW128((uint32_t)((b_row0 + np * 16) * 128 + kb + b_colb)));
#pragma unroll
            for (int mt = 0; mt < 4; ++mt)
#pragma unroll
                for (int nt = 0; nt < 8; ++nt)
                    mma_bf16(acc[mt][nt], afr[mt],
                             bfr[nt >> 1][(nt & 1) * 2], bfr[nt >> 1][(nt & 1) * 2 + 1]);
        }
        __syncthreads();
    }

    const int g = lane >> 2, tg = lane & 3;
#pragma unroll
    for (int mt = 0; mt < 4; ++mt) {
#pragma unroll
        for (int nt = 0; nt < 8; ++nt) {
            const int m0 = bm + wm * 64 + mt * 16 + g;
            const int n0 = bn + wn * 64 + nt * 8 + tg * 2;
            float* C = Cout + (size_t)m0 * N + n0;
            *(float2*)C = make_float2(acc[mt][nt][0] * scale, acc[mt][nt][1] * scale);
            *(float2*)(C + 8 * (size_t)N) = make_float2(acc[mt][nt][2] * scale, acc[mt][nt][3] * scale);
        }
    }
}

// ======================= conversion / transpose ==============================
__global__ void cvt_bf16_kernel(const float* __restrict__ in,
                                __nv_bfloat16* __restrict__ out, int n4)
{
    int i = blockIdx.x * blockDim.x + threadIdx.x;
    if (i < n4) {
        float4 v = *(const float4*)(in + i * 4);
        __nv_bfloat162* o = (__nv_bfloat162*)(out + i * 4);
        o[0] = __floats2bfloat162_rn(v.x, v.y);
        o[1] = __floats2bfloat162_rn(v.z, v.w);
    }
}

// Fused transpose of all 6 weight matrices; jobs passed BY VALUE (graph-safe).
struct TransJob { const float* in; __nv_bfloat16* out; int R, C; };
struct TransJobs6 { TransJob j[6]; };

__global__ void transpose_all_kernel(TransJobs6 jobs)
{
    __shared__ float tile[32][33];
    const TransJob j = jobs.j[blockIdx.z];
    const int c0 = blockIdx.x * 32, r0 = blockIdx.y * 32;
    if (c0 >= j.C || r0 >= j.R) return;
    const int tx = threadIdx.x, ty = threadIdx.y;
#pragma unroll
    for (int i = ty; i < 32; i += 8)
        tile[i][tx] = j.in[(size_t)(r0 + i) * j.C + c0 + tx];
    __syncthreads();
#pragma unroll
    for (int i = ty; i < 32; i += 8)
        j.out[(size_t)(c0 + i) * j.R + r0 + tx] = __float2bfloat16(tile[tx][i]);
}

// ======================= normalize: fp32 in -> bf16 unit rows ================
__global__ void normalize_bf_kernel(const float* __restrict__ x,
                                    __nv_bfloat16* __restrict__ y)
{
    __shared__ float red[128];
    const int row = blockIdx.x, tid = threadIdx.x;
    const float* p = x + (size_t)row * PROJ;
    __nv_bfloat16* q = y + (size_t)row * PROJ;
    float s = 0.f;
    for (int j = tid; j < PROJ; j += 128) { float v = p[j]; s += v * v; }
    red[tid] = s; __syncthreads();
    for (int off = 64; off > 0; off >>= 1) {
        if (tid < off) red[tid] += red[tid + off];
        __syncthreads();
    }
    const float r = rsqrtf(red[0]);
    for (int j = tid; j < PROJ; j += 128) q[j] = __float2bfloat16(p[j] * r);
}

// ======================= mining + weighted CE ================================
__device__ __forceinline__ unsigned mono(float f)
{
    unsigned u = __float_as_uint(f);
    return (u & 0x80000000u) ? ~u : (u | 0x80000000u);
}

__global__ __launch_bounds__(256)
void mine_loss_kernel(const float* __restrict__ sim, const float* __restrict__ mw,
                      float* __restrict__ ce_out, int modal)
{
    __shared__ float    sh[B_SZ];
    __shared__ unsigned hist[256];
    __shared__ float    red[256];
    __shared__ unsigned s_prefix;
    __shared__ int      s_kth;

    const int row  = blockIdx.x;
    const int tid  = threadIdx.x;
    const int lane = tid & 31;
    const float* srow = sim + (size_t)row * B_SZ;

    for (int j = tid; j < B_SZ; j += 256) sh[j] = srow[j];
    __syncthreads();

    unsigned prefix = 0, pmask = 0;
    int kth = KSEL;
#pragma unroll
    for (int pass = 3; pass >= 0; --pass) {
        const int shift = pass * 8;
        hist[tid] = 0;
        __syncthreads();
        for (int j = tid; j < B_SZ; j += 256) {
            float s = sh[j];
            unsigned u = (j == row || s > 9.0f) ? 0u : mono(s);
            unsigned bin = ((u & pmask) == prefix) ? ((u >> shift) & 255u) : 0xFFFFFFFFu;
            unsigned peers = __match_any_sync(0xFFFFFFFFu, bin);
            if (bin != 0xFFFFFFFFu && lane == (unsigned)(__ffs(peers) - 1))
                atomicAdd(&hist[bin], (unsigned)__popc(peers));
        }
        __syncthreads();
        if (tid == 0) {
            int acc = 0, b = 255;
            for (;; --b) { acc += (int)hist[b]; if (acc >= kth || b == 0) break; }
            s_prefix = prefix | ((unsigned)b << shift);
            s_kth    = kth - (acc - (int)hist[b]);
        }
        __syncthreads();
        prefix = s_prefix; kth = s_kth;
        pmask |= (0xFFu << shift);
    }
    const unsigned thr = prefix;

    float vmax = -3.402823466e38f;
    for (int j = tid; j < B_SZ; j += 256) {
        float s = sh[j];
        bool diag  = (j == row);
        bool noise = (!diag) && (s > 9.0f);
        float w;
        if (noise)                        w = 0.5f;
        else if (!diag && mono(s) >= thr) w = 1.5f;
        else                              w = 1.0f;
        float v = s * w;
        sh[j] = v;
        vmax = fmaxf(vmax, v);
    }
    red[tid] = vmax; __syncthreads();
    for (int off = 128; off > 0; off >>= 1) {
        if (tid < off) red[tid] = fmaxf(red[tid], red[tid + off]);
        __syncthreads();
    }
    const float vm = red[0];
    __syncthreads();

    float ssum = 0.f;
    for (int j = tid; j < B_SZ; j += 256) ssum += expf(sh[j] - vm);
    red[tid] = ssum; __syncthreads();
    for (int off = 128; off > 0; off >>= 1) {
        if (tid < off) red[tid] += red[tid + off];
        __syncthreads();
    }
    if (tid == 0) {
        float lse = vm + logf(red[0]);
        float ce  = lse - sh[row];
        ce_out[modal * B_SZ + row] = ce * mw[(size_t)row * 2 + modal];
    }
}

__global__ void finalize_kernel(const float* __restrict__ ce, float* __restrict__ out)
{
    __shared__ float red[256];
    const int tid = threadIdx.x;
    float s = 0.f;
    for (int j = tid; j < 2 * B_SZ; j += 256) s += ce[j];
    red[tid] = s; __syncthreads();
    for (int off = 128; off > 0; off >>= 1) {
        if (tid < off) red[tid] += red[tid + off];
        __syncthreads();
    }
    if (tid == 0) out[0] = red[0] * (0.5f / (float)B_SZ);
}

// ======================= launch ==============================================
extern "C" void kernel_launch(void* const* d_in, const int* in_sizes, int n_in,
                              void* d_out, int out_size)
{
    const float* id_emb = (const float*)d_in[0];
    const float* text   = (const float*)d_in[1];
    const float* vis    = (const float*)d_in[2];
    const float* mw     = (const float*)d_in[3];
    const float* Wa_t = (const float*)d_in[4];  const float* ba_t = (const float*)d_in[5];
    const float* Wa_v = (const float*)d_in[6];  const float* ba_v = (const float*)d_in[7];
    const float* W1_t = (const float*)d_in[8];  const float* b1_t = (const float*)d_in[9];
    const float* W2_t = (const float*)d_in[10]; const float* b2_t = (const float*)d_in[11];
    const float* W1_v = (const float*)d_in[12]; const float* b1_v = (const float*)d_in[13];
    const float* W2_v = (const float*)d_in[14]; const float* b2_v = (const float*)d_in[15];

    __nv_bfloat16 *wa_t, *wa_v, *w1_t, *w1_v, *w2_t, *w2_v;
    __nv_bfloat16 *id_bf, *in_bf, *feat_bf, *h_bf, *mproj, *iproj;
    float *projf, *sim, *ce;
    cudaGetSymbolAddress((void**)&wa_t, g_Wa_t);   cudaGetSymbolAddress((void**)&wa_v, g_Wa_v);
    cudaGetSymbolAddress((void**)&w1_t, g_W1_t);   cudaGetSymbolAddress((void**)&w1_v, g_W1_v);
    cudaGetSymbolAddress((void**)&w2_t, g_W2_t);   cudaGetSymbolAddress((void**)&w2_v, g_W2_v);
    cudaGetSymbolAddress((void**)&id_bf, g_id_bf); cudaGetSymbolAddress((void**)&in_bf, g_in_bf);
    cudaGetSymbolAddress((void**)&feat_bf, g_feat_bf); cudaGetSymbolAddress((void**)&h_bf, g_h_bf);
    cudaGetSymbolAddress((void**)&projf, g_projf);
    cudaGetSymbolAddress((void**)&mproj, g_mproj); cudaGetSymbolAddress((void**)&iproj, g_iproj);
    cudaGetSymbolAddress((void**)&sim, g_sim);     cudaGetSymbolAddress((void**)&ce, g_ce);

    cudaFuncSetAttribute(hmma_gemm<false, true, true>,
                         cudaFuncAttributeMaxDynamicSharedMemorySize, TC_DSMEM);
    cudaFuncSetAttribute(hmma_gemm<true, true, true>,
                         cudaFuncAttributeMaxDynamicSharedMemorySize, TC_DSMEM);
    cudaFuncSetAttribute(hmma_gemm<false, true, false>,
                         cudaFuncAttributeMaxDynamicSharedMemorySize, TC_DSMEM);
    cudaFuncSetAttribute(hmma_gemm_256,
                         cudaFuncAttributeMaxDynamicSharedMemorySize, TC_DSMEM_256);

    // Fused weight transposes — jobs passed by value (graph-capture safe)
    {
        TransJobs6 jobs = {{
            { Wa_t, wa_t, 768,  HID  },
            { Wa_v, wa_v, 2048, HID  },
            { W1_t, w1_t, HID,  HID  },
            { W1_v, w1_v, HID,  HID  },
            { W2_t, w2_t, HID,  PROJ },
            { W2_v, w2_v, HID,  PROJ },
        }};
        transpose_all_kernel<<<dim3(HID / 32, 2048 / 32, 6), dim3(32, 8)>>>(jobs);
    }
    cvt_bf16_kernel<<<(B_SZ * HID / 4 + 255) / 256, 256>>>(id_emb, id_bf, B_SZ * HID / 4);

    struct Modal {
        const float* f; int kf;
        const __nv_bfloat16 *wa, *w1, *w2;
        const float *ba, *b1, *b2;
    };
    const Modal ms[2] = {
        { text,  768, wa_t, w1_t, w2_t, ba_t, b1_t, b2_t },   // modal 0 = text
        { vis,  2048, wa_v, w1_v, w2_v, ba_v, b1_v, b2_v },   // modal 1 = visual
    };

    for (int m = 0; m < 2; m++) {
        const int KF = ms[m].kf;
        cvt_bf16_kernel<<<(B_SZ * KF / 4 + 255) / 256, 256>>>(ms[m].f, in_bf, B_SZ * KF / 4);
        // adapter: feat = in @ Wa + ba (bf16 out)
        hmma_gemm<false, true, true><<<dim3(HID / 128, B_SZ / 128), 256, TC_DSMEM>>>(
            in_bf, ms[m].wa, ms[m].ba, feat_bf, B_SZ, HID, KF, 1.f);
        // modal projector
        hmma_gemm<true, true, true><<<dim3(HID / 128, B_SZ / 128), 256, TC_DSMEM>>>(
            feat_bf, ms[m].w1, ms[m].b1, h_bf, B_SZ, HID, HID, 1.f);
        hmma_gemm<false, true, false><<<dim3(PROJ / 128, B_SZ / 128), 256, TC_DSMEM>>>(
            h_bf, ms[m].w2, ms[m].b2, projf, B_SZ, PROJ, HID, 1.f);
        normalize_bf_kernel<<<B_SZ, 128>>>(projf, mproj);
        // id projector
        hmma_gemm<true, true, true><<<dim3(HID / 128, B_SZ / 128), 256, TC_DSMEM>>>(
            id_bf, ms[m].w1, ms[m].b1, h_bf, B_SZ, HID, HID, 1.f);
        hmma_gemm<false, true, false><<<dim3(PROJ / 128, B_SZ / 128), 256, TC_DSMEM>>>(
            h_bf, ms[m].w2, ms[m].b2, projf, B_SZ, PROJ, HID, 1.f);
        normalize_bf_kernel<<<B_SZ, 128>>>(projf, iproj);
        // sim = (iproj @ mproj^T) * 10  (wide-tile GEMM)
        hmma_gemm_256<<<dim3(B_SZ / 256, B_SZ / 128), 256, TC_DSMEM_256>>>(
            iproj, mproj, sim, B_SZ, B_SZ, PROJ, 10.0f);
        mine_loss_kernel<<<B_SZ, 256>>>(sim, mw, ce, m);
    }
    finalize_kernel<<<1, 256>>>(ce, (float*)d_out);
}

// round 8
// speedup vs baseline: 4.0964x; 1.1909x over previous
#include <cuda_runtime.h>
#include <cuda_bf16.h>
#include <cstdint>

#define B_SZ 8192
#define HID  1024
#define PROJ 512
#define KSEL 4096

// ======================= helpers =============================================
__device__ __forceinline__ uint32_t smem_to_u32(const void* p) {
    uint32_t a;
    asm("{ .reg .u64 t; cvta.to.shared.u64 t, %1; cvt.u32.u64 %0, t; }"
        : "=r"(a) : "l"(p));
    return a;
}
#define SW128(off) ((off) ^ (((off) >> 3) & 0x70))

__device__ __forceinline__ void cp_async16(uint32_t dst, const void* src) {
    asm volatile("cp.async.cg.shared.global [%0], [%1], 16;"
                 :: "r"(dst), "l"(src) : "memory");
}
__device__ __forceinline__ void ldsm_x4(uint32_t& r0, uint32_t& r1,
                                        uint32_t& r2, uint32_t& r3, uint32_t addr) {
    asm volatile("ldmatrix.sync.aligned.m8n8.x4.shared.b16 {%0,%1,%2,%3}, [%4];"
                 : "=r"(r0), "=r"(r1), "=r"(r2), "=r"(r3) : "r"(addr));
}
__device__ __forceinline__ void mma_bf16(float* c, const uint32_t* a,
                                         uint32_t b0, uint32_t b1) {
    asm volatile(
        "mma.sync.aligned.m16n8k16.row.col.f32.bf16.bf16.f32 "
        "{%0,%1,%2,%3}, {%4,%5,%6,%7}, {%8,%9}, {%0,%1,%2,%3};"
        : "+f"(c[0]), "+f"(c[1]), "+f"(c[2]), "+f"(c[3])
        : "r"(a[0]), "r"(a[1]), "r"(a[2]), "r"(a[3]), "r"(b0), "r"(b1));
}

// ======================= scratch (device globals) ============================
__device__ __align__(16) __nv_bfloat16 g_Wa_t[HID * 768];
__device__ __align__(16) __nv_bfloat16 g_Wa_v[HID * 2048];
__device__ __align__(16) __nv_bfloat16 g_W1_t[HID * HID];
__device__ __align__(16) __nv_bfloat16 g_W1_v[HID * HID];
__device__ __align__(16) __nv_bfloat16 g_W2_t[PROJ * HID];
__device__ __align__(16) __nv_bfloat16 g_W2_v[PROJ * HID];
__device__ __align__(16) __nv_bfloat16 g_id_bf[B_SZ * HID];
__device__ __align__(16) __nv_bfloat16 g_in_bf[B_SZ * 2048];
__device__ __align__(16) __nv_bfloat16 g_feat_bf[B_SZ * HID];
__device__ __align__(16) __nv_bfloat16 g_h_bf[B_SZ * HID];
__device__ __align__(16) float         g_projf[B_SZ * PROJ];
__device__ __align__(16) __nv_bfloat16 g_mproj[B_SZ * PROJ];
__device__ __align__(16) __nv_bfloat16 g_iproj[B_SZ * PROJ];
__device__ float g_sim[(size_t)B_SZ * B_SZ];
__device__ float g_ce[2 * B_SZ];

// ======================= HMMA GEMM (128x128 CTA tile) ========================
static constexpr int STAGES   = 3;
static constexpr int TC_DSMEM = STAGES * 32 * 1024 + 1024;

template <bool RELU, bool BIAS, bool OUT_BF16>
__global__ __launch_bounds__(256)
void hmma_gemm(const __nv_bfloat16* __restrict__ A, const __nv_bfloat16* __restrict__ Bw,
               const float* __restrict__ bias, void* __restrict__ Cout,
               int M, int N, int K, float scale)
{
    extern __shared__ char dsm[];
    const uint32_t base_u  = smem_to_u32(dsm);
    const uint32_t tiles_u = (base_u + 1023u) & ~1023u;

    const int tid  = threadIdx.x;
    const int wid  = tid >> 5, lane = tid & 31;
    const int wm   = wid >> 2, wn = wid & 3;
    const int bm   = blockIdx.y * 128, bn = blockIdx.x * 128;
    const int nsteps = K >> 6;

    float acc[4][4][4];
#pragma unroll
    for (int i = 0; i < 4; i++)
#pragma unroll
        for (int j = 0; j < 4; j++)
#pragma unroll
            for (int r = 0; r < 4; r++) acc[i][j][r] = 0.f;

    const int lr = tid >> 3;
    const int lc = tid & 7;

    auto load_stage = [&](int buf, int k0) {
        const uint32_t tA = tiles_u + (uint32_t)buf * 32768u;
        const uint32_t tB = tA + 16384u;
#pragma unroll
        for (int h = 0; h < 4; h++) {
            int r = lr + h * 32;
            uint32_t sw = SW128((uint32_t)(r * 128 + lc * 16));
            cp_async16(tA + sw, A  + (size_t)(bm + r) * K + k0 + lc * 8);
            cp_async16(tB + sw, Bw + (size_t)(bn + r) * K + k0 + lc * 8);
        }
    };

    const int a_row  = wm * 64 + (lane & 15);
    const int a_colb = (lane >> 4) << 4;
    const int b_row0 = wn * 32 + (lane & 7) + ((lane >> 4) << 3);
    const int b_colb = ((lane >> 3) & 1) << 4;

    auto ld_frags = [&](uint32_t tA, uint32_t tB, int kk,
                        uint32_t a[4][4], uint32_t bf[2][4]) {
        const int kb = kk * 32;
#pragma unroll
        for (int mt = 0; mt < 4; ++mt)
            ldsm_x4(a[mt][0], a[mt][1], a[mt][2], a[mt][3],
                    tA + SW128((uint32_t)((a_row + mt * 16) * 128 + kb + a_colb)));
#pragma unroll
        for (int np = 0; np < 2; ++np)
            ldsm_x4(bf[np][0], bf[np][1], bf[np][2], bf[np][3],
                    tB + SW128((uint32_t)((b_row0 + np * 16) * 128 + kb + b_colb)));
    };

    load_stage(0, 0);
    asm volatile("cp.async.commit_group;" ::: "memory");
    if (nsteps > 1) load_stage(1, 64);
    asm volatile("cp.async.commit_group;" ::: "memory");

    uint32_t afr[2][4][4], bfr[2][2][4];

    for (int s = 0; s < nsteps; ++s) {
        asm volatile("cp.async.wait_group 1;" ::: "memory");
        __syncthreads();

        if (s + 2 < nsteps) load_stage((s + 2) % STAGES, (s + 2) << 6);
        asm volatile("cp.async.commit_group;" ::: "memory");

        const uint32_t tA = tiles_u + (uint32_t)(s % STAGES) * 32768u;
        const uint32_t tB = tA + 16384u;

        ld_frags(tA, tB, 0, afr[0], bfr[0]);
#pragma unroll
        for (int kk = 0; kk < 4; ++kk) {
            const int cur = kk & 1;
            if (kk < 3) ld_frags(tA, tB, kk + 1, afr[cur ^ 1], bfr[cur ^ 1]);
#pragma unroll
            for (int mt = 0; mt < 4; ++mt)
#pragma unroll
                for (int nt = 0; nt < 4; ++nt)
                    mma_bf16(acc[mt][nt], afr[cur][mt],
                             bfr[cur][nt >> 1][(nt & 1) * 2],
                             bfr[cur][nt >> 1][(nt & 1) * 2 + 1]);
        }
        __syncthreads();
    }

    const int g = lane >> 2, tg = lane & 3;
#pragma unroll
    for (int mt = 0; mt < 4; ++mt) {
#pragma unroll
        for (int nt = 0; nt < 4; ++nt) {
            const int m0 = bm + wm * 64 + mt * 16 + g;
            const int n0 = bn + wn * 32 + nt * 8 + tg * 2;
            float v0 = acc[mt][nt][0], v1 = acc[mt][nt][1];
            float v2 = acc[mt][nt][2], v3 = acc[mt][nt][3];
            if (BIAS) {
                float bb0 = bias[n0], bb1 = bias[n0 + 1];
                v0 += bb0; v1 += bb1; v2 += bb0; v3 += bb1;
            }
            v0 *= scale; v1 *= scale; v2 *= scale; v3 *= scale;
            if (RELU) {
                v0 = fmaxf(v0, 0.f); v1 = fmaxf(v1, 0.f);
                v2 = fmaxf(v2, 0.f); v3 = fmaxf(v3, 0.f);
            }
            if (OUT_BF16) {
                __nv_bfloat16* C = (__nv_bfloat16*)Cout;
                *(__nv_bfloat162*)(C + (size_t)m0 * N + n0)       = __floats2bfloat162_rn(v0, v1);
                *(__nv_bfloat162*)(C + (size_t)(m0 + 8) * N + n0) = __floats2bfloat162_rn(v2, v3);
            } else {
                float* C = (float*)Cout;
                *(float2*)(C + (size_t)m0 * N + n0)       = make_float2(v0, v1);
                *(float2*)(C + (size_t)(m0 + 8) * N + n0) = make_float2(v2, v3);
            }
        }
    }
}

// ======================= HMMA GEMM (128x256 CTA tile, sim only) ==============
static constexpr int ST256        = 3;
static constexpr int STAGE_BYTES  = 48 * 1024;
static constexpr int TC_DSMEM_256 = ST256 * STAGE_BYTES + 1024;

__global__ __launch_bounds__(256, 1)
void hmma_gemm_256(const __nv_bfloat16* __restrict__ A, const __nv_bfloat16* __restrict__ Bw,
                   float* __restrict__ Cout, int M, int N, int K, float scale)
{
    extern __shared__ char dsm[];
    const uint32_t base_u  = smem_to_u32(dsm);
    const uint32_t tiles_u = (base_u + 1023u) & ~1023u;

    const int tid  = threadIdx.x;
    const int wid  = tid >> 5, lane = tid & 31;
    const int wm   = wid >> 2, wn = wid & 3;
    const int bm   = blockIdx.y * 128, bn = blockIdx.x * 256;
    const int nsteps = K >> 6;

    float acc[4][8][4];
#pragma unroll
    for (int i = 0; i < 4; i++)
#pragma unroll
        for (int j = 0; j < 8; j++)
#pragma unroll
            for (int r = 0; r < 4; r++) acc[i][j][r] = 0.f;

    const int lr = tid >> 3;
    const int lc = tid & 7;

    auto load_stage = [&](int buf, int k0) {
        const uint32_t tA = tiles_u + (uint32_t)buf * (uint32_t)STAGE_BYTES;
        const uint32_t tB = tA + 16384u;
#pragma unroll
        for (int h = 0; h < 4; h++) {
            int r = lr + h * 32;
            uint32_t sw = SW128((uint32_t)(r * 128 + lc * 16));
            cp_async16(tA + sw, A + (size_t)(bm + r) * K + k0 + lc * 8);
        }
#pragma unroll
        for (int h = 0; h < 8; h++) {
            int r = lr + h * 32;
            uint32_t sw = SW128((uint32_t)(r * 128 + lc * 16));
            cp_async16(tB + sw, Bw + (size_t)(bn + r) * K + k0 + lc * 8);
        }
        asm volatile("cp.async.commit_group;" ::: "memory");
    };

    const int a_row  = wm * 64 + (lane & 15);
    const int a_colb = (lane >> 4) << 4;
    const int b_row0 = wn * 64 + (lane & 7) + ((lane >> 4) << 3);
    const int b_colb = ((lane >> 3) & 1) << 4;

    load_stage(0, 0);
    if (nsteps > 1) load_stage(1, 64);

    for (int s = 0; s < nsteps; ++s) {
        asm volatile("cp.async.wait_group 1;" ::: "memory");
        __syncthreads();

        if (s + 2 < nsteps) load_stage((s + 2) % ST256, (s + 2) << 6);
        else                asm volatile("cp.async.commit_group;" ::: "memory");

        const uint32_t tA = tiles_u + (uint32_t)(s % ST256) * (uint32_t)STAGE_BYTES;
        const uint32_t tB = tA + 16384u;

#pragma unroll
        for (int kk = 0; kk < 4; ++kk) {
            const int kb = kk * 32;
            uint32_t afr[4][4];
#pragma unroll
            for (int mt = 0; mt < 4; ++mt)
                ldsm_x4(afr[mt][0], afr[mt][1], afr[mt][2], afr[mt][3],
                        tA + SW128((uint32_t)((a_row + mt * 16) * 128 + kb + a_colb)));
            uint32_t bfr[4][4];
#pragma unroll
            for (int np = 0; np < 4; ++np)
                ldsm_x4(bfr[np][0], bfr[np][1], bfr[np][2], bfr[np][3],
                        tB + SW128((uint32_t)((b_row0 + np * 16) * 128 + kb + b_colb)));
#pragma unroll
            for (int mt = 0; mt < 4; ++mt)
#pragma unroll
                for (int nt = 0; nt < 8; ++nt)
                    mma_bf16(acc[mt][nt], afr[mt],
                             bfr[nt >> 1][(nt & 1) * 2], bfr[nt >> 1][(nt & 1) * 2 + 1]);
        }
        __syncthreads();
    }

    const int g = lane >> 2, tg = lane & 3;
#pragma unroll
    for (int mt = 0; mt < 4; ++mt) {
#pragma unroll
        for (int nt = 0; nt < 8; ++nt) {
            const int m0 = bm + wm * 64 + mt * 16 + g;
            const int n0 = bn + wn * 64 + nt * 8 + tg * 2;
            float* C = Cout + (size_t)m0 * N + n0;
            *(float2*)C = make_float2(acc[mt][nt][0] * scale, acc[mt][nt][1] * scale);
            *(float2*)(C + 8 * (size_t)N) = make_float2(acc[mt][nt][2] * scale, acc[mt][nt][3] * scale);
        }
    }
}

// ======================= conversion / transpose ==============================
__global__ void cvt_bf16_kernel(const float* __restrict__ in,
                                __nv_bfloat16* __restrict__ out, int n4)
{
    int i = blockIdx.x * blockDim.x + threadIdx.x;
    if (i < n4) {
        float4 v = *(const float4*)(in + i * 4);
        __nv_bfloat162* o = (__nv_bfloat162*)(out + i * 4);
        o[0] = __floats2bfloat162_rn(v.x, v.y);
        o[1] = __floats2bfloat162_rn(v.z, v.w);
    }
}

struct TransJob { const float* in; __nv_bfloat16* out; int R, C; };
struct TransJobs6 { TransJob j[6]; };

__global__ void transpose_all_kernel(TransJobs6 jobs)
{
    __shared__ float tile[32][33];
    const TransJob j = jobs.j[blockIdx.z];
    const int c0 = blockIdx.x * 32, r0 = blockIdx.y * 32;
    if (c0 >= j.C || r0 >= j.R) return;
    const int tx = threadIdx.x, ty = threadIdx.y;
#pragma unroll
    for (int i = ty; i < 32; i += 8)
        tile[i][tx] = j.in[(size_t)(r0 + i) * j.C + c0 + tx];
    __syncthreads();
#pragma unroll
    for (int i = ty; i < 32; i += 8)
        j.out[(size_t)(c0 + i) * j.R + r0 + tx] = __float2bfloat16(tile[tx][i]);
}

// ======================= normalize: fp32 in -> bf16 unit rows ================
__global__ void normalize_bf_kernel(const float* __restrict__ x,
                                    __nv_bfloat16* __restrict__ y)
{
    __shared__ float red[128];
    const int row = blockIdx.x, tid = threadIdx.x;
    const float* p = x + (size_t)row * PROJ;
    __nv_bfloat16* q = y + (size_t)row * PROJ;
    float s = 0.f;
    for (int j = tid; j < PROJ; j += 128) { float v = p[j]; s += v * v; }
    red[tid] = s; __syncthreads();
    for (int off = 64; off > 0; off >>= 1) {
        if (tid < off) red[tid] += red[tid + off];
        __syncthreads();
    }
    const float r = rsqrtf(red[0]);
    for (int j = tid; j < PROJ; j += 128) q[j] = __float2bfloat16(p[j] * r);
}

// ======================= mining + weighted CE (v2) ============================
// 3-pass radix select (11/11/10-bit digits, 2048-bin histogram) with parallel
// suffix-scan bin selection; fast exp/log for the logsumexp.
__device__ __forceinline__ unsigned mono(float f)
{
    unsigned u = __float_as_uint(f);
    return (u & 0x80000000u) ? ~u : (u | 0x80000000u);
}

__global__ __launch_bounds__(256)
void mine_loss_kernel(const float* __restrict__ sim, const float* __restrict__ mw,
                      float* __restrict__ ce_out, int modal)
{
    __shared__ float    sh[B_SZ];        // 32 KB
    __shared__ unsigned hist[2048];      // 8 KB
    __shared__ unsigned part[256];
    __shared__ float    red[256];
    __shared__ unsigned s_prefix;
    __shared__ int      s_kth;

    const int row  = blockIdx.x;
    const int tid  = threadIdx.x;
    const int lane = tid & 31;

    // vectorized row load
    const float4* srow4 = (const float4*)(sim + (size_t)row * B_SZ);
    for (int j = tid; j < B_SZ / 4; j += 256)
        *(float4*)&sh[j * 4] = srow4[j];
    __syncthreads();

    unsigned prefix = 0, pmask = 0;
    int kth = KSEL;
    const int      pshift[3] = {21, 10, 0};
    const unsigned pdmask[3] = {0x7FFu, 0x7FFu, 0x3FFu};

#pragma unroll
    for (int pass = 0; pass < 3; ++pass) {
        const int shift      = pshift[pass];
        const unsigned dmask = pdmask[pass];

        for (int i = tid; i < 2048; i += 256) hist[i] = 0;
        __syncthreads();

        for (int j = tid; j < B_SZ; j += 256) {
            float s = sh[j];
            unsigned u = (j == row || s > 9.0f) ? 0u : mono(s);
            unsigned bin = ((u & pmask) == prefix) ? ((u >> shift) & dmask) : 0xFFFFFFFFu;
            unsigned peers = __match_any_sync(0xFFFFFFFFu, bin);
            if (bin != 0xFFFFFFFFu && lane == (unsigned)(__ffs(peers) - 1))
                atomicAdd(&hist[bin], (unsigned)__popc(peers));
        }
        __syncthreads();

        // parallel selection: largest bin b with suffix_sum(b) >= kth
        unsigned loc[8];
        unsigned tot = 0;
#pragma unroll
        for (int i = 7; i >= 0; --i) { tot += hist[tid * 8 + i]; loc[i] = tot; }
        part[tid] = tot;
        __syncthreads();
#pragma unroll
        for (int off = 1; off < 256; off <<= 1) {
            unsigned u2 = (tid + off < 256) ? part[tid + off] : 0u;
            __syncthreads();
            part[tid] += u2;
            __syncthreads();
        }
        const unsigned above = part[tid] - tot;      // sum over threads > tid
        if (above < (unsigned)kth && loc[0] + above >= (unsigned)kth) {
            int bi = 0;
#pragma unroll
            for (int i = 7; i >= 1; --i)
                if (loc[i] + above >= (unsigned)kth) { bi = i; break; }
            const unsigned nb = (bi < 7) ? loc[bi + 1] : 0u;  // suffix(b+1) minus 'above'
            s_prefix = prefix | ((unsigned)(tid * 8 + bi) << shift);
            s_kth    = kth - (int)(nb + above);
        }
        __syncthreads();
        prefix = s_prefix; kth = s_kth;
        pmask |= (dmask << shift);
        __syncthreads();
    }
    const unsigned thr = prefix;   // key of the KSEL-th largest

    // weights + in-place weighted values; row max
    float vmax = -3.402823466e38f;
    for (int j = tid; j < B_SZ; j += 256) {
        float s = sh[j];
        bool diag  = (j == row);
        bool noise = (!diag) && (s > 9.0f);
        float w;
        if (noise)                        w = 0.5f;
        else if (!diag && mono(s) >= thr) w = 1.5f;
        else                              w = 1.0f;
        float v = s * w;
        sh[j] = v;
        vmax = fmaxf(vmax, v);
    }
    red[tid] = vmax; __syncthreads();
    for (int off = 128; off > 0; off >>= 1) {
        if (tid < off) red[tid] = fmaxf(red[tid], red[tid + off]);
        __syncthreads();
    }
    const float vm = red[0];
    __syncthreads();

    float ssum = 0.f;
    for (int j = tid; j < B_SZ; j += 256) ssum += __expf(sh[j] - vm);
    red[tid] = ssum; __syncthreads();
    for (int off = 128; off > 0; off >>= 1) {
        if (tid < off) red[tid] += red[tid + off];
        __syncthreads();
    }
    if (tid == 0) {
        float lse = vm + __logf(red[0]);
        float ce  = lse - sh[row];
        ce_out[modal * B_SZ + row] = ce * mw[(size_t)row * 2 + modal];
    }
}

__global__ void finalize_kernel(const float* __restrict__ ce, float* __restrict__ out)
{
    __shared__ float red[256];
    const int tid = threadIdx.x;
    float s = 0.f;
    for (int j = tid; j < 2 * B_SZ; j += 256) s += ce[j];
    red[tid] = s; __syncthreads();
    for (int off = 128; off > 0; off >>= 1) {
        if (tid < off) red[tid] += red[tid + off];
        __syncthreads();
    }
    if (tid == 0) out[0] = red[0] * (0.5f / (float)B_SZ);
}

// ======================= launch ==============================================
extern "C" void kernel_launch(void* const* d_in, const int* in_sizes, int n_in,
                              void* d_out, int out_size)
{
    const float* id_emb = (const float*)d_in[0];
    const float* text   = (const float*)d_in[1];
    const float* vis    = (const float*)d_in[2];
    const float* mw     = (const float*)d_in[3];
    const float* Wa_t = (const float*)d_in[4];  const float* ba_t = (const float*)d_in[5];
    const float* Wa_v = (const float*)d_in[6];  const float* ba_v = (const float*)d_in[7];
    const float* W1_t = (const float*)d_in[8];  const float* b1_t = (const float*)d_in[9];
    const float* W2_t = (const float*)d_in[10]; const float* b2_t = (const float*)d_in[11];
    const float* W1_v = (const float*)d_in[12]; const float* b1_v = (const float*)d_in[13];
    const float* W2_v = (const float*)d_in[14]; const float* b2_v = (const float*)d_in[15];

    __nv_bfloat16 *wa_t, *wa_v, *w1_t, *w1_v, *w2_t, *w2_v;
    __nv_bfloat16 *id_bf, *in_bf, *feat_bf, *h_bf, *mproj, *iproj;
    float *projf, *sim, *ce;
    cudaGetSymbolAddress((void**)&wa_t, g_Wa_t);   cudaGetSymbolAddress((void**)&wa_v, g_Wa_v);
    cudaGetSymbolAddress((void**)&w1_t, g_W1_t);   cudaGetSymbolAddress((void**)&w1_v, g_W1_v);
    cudaGetSymbolAddress((void**)&w2_t, g_W2_t);   cudaGetSymbolAddress((void**)&w2_v, g_W2_v);
    cudaGetSymbolAddress((void**)&id_bf, g_id_bf); cudaGetSymbolAddress((void**)&in_bf, g_in_bf);
    cudaGetSymbolAddress((void**)&feat_bf, g_feat_bf); cudaGetSymbolAddress((void**)&h_bf, g_h_bf);
    cudaGetSymbolAddress((void**)&projf, g_projf);
    cudaGetSymbolAddress((void**)&mproj, g_mproj); cudaGetSymbolAddress((void**)&iproj, g_iproj);
    cudaGetSymbolAddress((void**)&sim, g_sim);     cudaGetSymbolAddress((void**)&ce, g_ce);

    cudaFuncSetAttribute(hmma_gemm<false, true, true>,
                         cudaFuncAttributeMaxDynamicSharedMemorySize, TC_DSMEM);
    cudaFuncSetAttribute(hmma_gemm<true, true, true>,
                         cudaFuncAttributeMaxDynamicSharedMemorySize, TC_DSMEM);
    cudaFuncSetAttribute(hmma_gemm<false, true, false>,
                         cudaFuncAttributeMaxDynamicSharedMemorySize, TC_DSMEM);
    cudaFuncSetAttribute(hmma_gemm_256,
                         cudaFuncAttributeMaxDynamicSharedMemorySize, TC_DSMEM_256);

    {
        TransJobs6 jobs = {{
            { Wa_t, wa_t, 768,  HID  },
            { Wa_v, wa_v, 2048, HID  },
            { W1_t, w1_t, HID,  HID  },
            { W1_v, w1_v, HID,  HID  },
            { W2_t, w2_t, HID,  PROJ },
            { W2_v, w2_v, HID,  PROJ },
        }};
        transpose_all_kernel<<<dim3(HID / 32, 2048 / 32, 6), dim3(32, 8)>>>(jobs);
    }
    cvt_bf16_kernel<<<(B_SZ * HID / 4 + 255) / 256, 256>>>(id_emb, id_bf, B_SZ * HID / 4);

    struct Modal {
        const float* f; int kf;
        const __nv_bfloat16 *wa, *w1, *w2;
        const float *ba, *b1, *b2;
    };
    const Modal ms[2] = {
        { text,  768, wa_t, w1_t, w2_t, ba_t, b1_t, b2_t },
        { vis,  2048, wa_v, w1_v, w2_v, ba_v, b1_v, b2_v },
    };

    for (int m = 0; m < 2; m++) {
        const int KF = ms[m].kf;
        cvt_bf16_kernel<<<(B_SZ * KF / 4 + 255) / 256, 256>>>(ms[m].f, in_bf, B_SZ * KF / 4);
        hmma_gemm<false, true, true><<<dim3(HID / 128, B_SZ / 128), 256, TC_DSMEM>>>(
            in_bf, ms[m].wa, ms[m].ba, feat_bf, B_SZ, HID, KF, 1.f);
        hmma_gemm<true, true, true><<<dim3(HID / 128, B_SZ / 128), 256, TC_DSMEM>>>(
            feat_bf, ms[m].w1, ms[m].b1, h_bf, B_SZ, HID, HID, 1.f);
        hmma_gemm<false, true, false><<<dim3(PROJ / 128, B_SZ / 128), 256, TC_DSMEM>>>(
            h_bf, ms[m].w2, ms[m].b2, projf, B_SZ, PROJ, HID, 1.f);
        normalize_bf_kernel<<<B_SZ, 128>>>(projf, mproj);
        hmma_gemm<true, true, true><<<dim3(HID / 128, B_SZ / 128), 256, TC_DSMEM>>>(
            id_bf, ms[m].w1, ms[m].b1, h_bf, B_SZ, HID, HID, 1.f);
        hmma_gemm<false, true, false><<<dim3(PROJ / 128, B_SZ / 128), 256, TC_DSMEM>>>(
            h_bf, ms[m].w2, ms[m].b2, projf, B_SZ, PROJ, HID, 1.f);
        normalize_bf_kernel<<<B_SZ, 128>>>(projf, iproj);
        hmma_gemm_256<<<dim3(B_SZ / 256, B_SZ / 128), 256, TC_DSMEM_256>>>(
            iproj, mproj, sim, B_SZ, B_SZ, PROJ, 10.0f);
        mine_loss_kernel<<<B_SZ, 256>>>(sim, mw, ce, m);
    }
    finalize_kernel<<<1, 256>>>(ce, (float*)d_out);
}

// round 9
// speedup vs baseline: 4.3756x; 1.0682x over previous
#include <cuda_runtime.h>
#include <cuda_bf16.h>
#include <cstdint>

#define B_SZ 8192
#define HID  1024
#define PROJ 512
#define KSEL 4096

// ======================= helpers =============================================
__device__ __forceinline__ uint32_t smem_to_u32(const void* p) {
    uint32_t a;
    asm("{ .reg .u64 t; cvta.to.shared.u64 t, %1; cvt.u32.u64 %0, t; }"
        : "=r"(a) : "l"(p));
    return a;
}
#define SW128(off) ((off) ^ (((off) >> 3) & 0x70))

__device__ __forceinline__ void cp_async16(uint32_t dst, const void* src) {
    asm volatile("cp.async.cg.shared.global [%0], [%1], 16;"
                 :: "r"(dst), "l"(src) : "memory");
}
__device__ __forceinline__ void ldsm_x4(uint32_t& r0, uint32_t& r1,
                                        uint32_t& r2, uint32_t& r3, uint32_t addr) {
    asm volatile("ldmatrix.sync.aligned.m8n8.x4.shared.b16 {%0,%1,%2,%3}, [%4];"
                 : "=r"(r0), "=r"(r1), "=r"(r2), "=r"(r3) : "r"(addr));
}
__device__ __forceinline__ void mma_bf16(float* c, const uint32_t* a,
                                         uint32_t b0, uint32_t b1) {
    asm volatile(
        "mma.sync.aligned.m16n8k16.row.col.f32.bf16.bf16.f32 "
        "{%0,%1,%2,%3}, {%4,%5,%6,%7}, {%8,%9}, {%0,%1,%2,%3};"
        : "+f"(c[0]), "+f"(c[1]), "+f"(c[2]), "+f"(c[3])
        : "r"(a[0]), "r"(a[1]), "r"(a[2]), "r"(a[3]), "r"(b0), "r"(b1));
}

// ======================= scratch (device globals) ============================
__device__ __align__(16) __nv_bfloat16 g_Wa_t[HID * 768];
__device__ __align__(16) __nv_bfloat16 g_Wa_v[HID * 2048];
__device__ __align__(16) __nv_bfloat16 g_W1_t[HID * HID];
__device__ __align__(16) __nv_bfloat16 g_W1_v[HID * HID];
__device__ __align__(16) __nv_bfloat16 g_W2_t[PROJ * HID];
__device__ __align__(16) __nv_bfloat16 g_W2_v[PROJ * HID];
__device__ __align__(16) __nv_bfloat16 g_id_bf[B_SZ * HID];
__device__ __align__(16) __nv_bfloat16 g_in_bf[B_SZ * 2048];
__device__ __align__(16) __nv_bfloat16 g_feat_bf[B_SZ * HID];
__device__ __align__(16) __nv_bfloat16 g_h_bf[B_SZ * HID];
__device__ __align__(16) float         g_projf[B_SZ * PROJ];
__device__ __align__(16) __nv_bfloat16 g_mproj[B_SZ * PROJ];
__device__ __align__(16) __nv_bfloat16 g_iproj[B_SZ * PROJ];
__device__ float g_sim[(size_t)B_SZ * B_SZ];
__device__ float g_ce[2 * B_SZ];

// ======================= HMMA GEMM (128x128 CTA tile, 2 stages, 2 CTA/SM) ====
static constexpr int STAGES   = 2;
static constexpr int TC_DSMEM = STAGES * 32 * 1024 + 1024;   // 66KB -> 2 CTAs/SM

template <bool RELU, bool BIAS, bool OUT_BF16>
__global__ __launch_bounds__(256, 2)
void hmma_gemm(const __nv_bfloat16* __restrict__ A, const __nv_bfloat16* __restrict__ Bw,
               const float* __restrict__ bias, void* __restrict__ Cout,
               int M, int N, int K, float scale)
{
    extern __shared__ char dsm[];
    const uint32_t base_u  = smem_to_u32(dsm);
    const uint32_t tiles_u = (base_u + 1023u) & ~1023u;

    const int tid  = threadIdx.x;
    const int wid  = tid >> 5, lane = tid & 31;
    const int wm   = wid >> 2, wn = wid & 3;          // 2 x 4 warp grid
    const int bm   = blockIdx.y * 128, bn = blockIdx.x * 128;
    const int nsteps = K >> 6;

    float acc[4][4][4];
#pragma unroll
    for (int i = 0; i < 4; i++)
#pragma unroll
        for (int j = 0; j < 4; j++)
#pragma unroll
            for (int r = 0; r < 4; r++) acc[i][j][r] = 0.f;

    const int lr = tid >> 3;
    const int lc = tid & 7;

    auto load_stage = [&](int buf, int k0) {
        const uint32_t tA = tiles_u + (uint32_t)buf * 32768u;
        const uint32_t tB = tA + 16384u;
#pragma unroll
        for (int h = 0; h < 4; h++) {
            int r = lr + h * 32;
            uint32_t sw = SW128((uint32_t)(r * 128 + lc * 16));
            cp_async16(tA + sw, A  + (size_t)(bm + r) * K + k0 + lc * 8);
            cp_async16(tB + sw, Bw + (size_t)(bn + r) * K + k0 + lc * 8);
        }
        asm volatile("cp.async.commit_group;" ::: "memory");
    };

    const int a_row  = wm * 64 + (lane & 15);
    const int a_colb = (lane >> 4) << 4;
    const int b_row0 = wn * 32 + (lane & 7) + ((lane >> 4) << 3);
    const int b_colb = ((lane >> 3) & 1) << 4;

    auto ld_frags = [&](uint32_t tA, uint32_t tB, int kk,
                        uint32_t a[4][4], uint32_t bf[2][4]) {
        const int kb = kk * 32;
#pragma unroll
        for (int mt = 0; mt < 4; ++mt)
            ldsm_x4(a[mt][0], a[mt][1], a[mt][2], a[mt][3],
                    tA + SW128((uint32_t)((a_row + mt * 16) * 128 + kb + a_colb)));
#pragma unroll
        for (int np = 0; np < 2; ++np)
            ldsm_x4(bf[np][0], bf[np][1], bf[np][2], bf[np][3],
                    tB + SW128((uint32_t)((b_row0 + np * 16) * 128 + kb + b_colb)));
    };

    load_stage(0, 0);

    uint32_t afr[2][4][4], bfr[2][2][4];

    for (int s = 0; s < nsteps; ++s) {
        // issue next stage's loads before waiting (overlap fetch with wait)
        if (s + 1 < nsteps) {
            load_stage((s + 1) & 1, (s + 1) << 6);
            asm volatile("cp.async.wait_group 1;" ::: "memory");
        } else {
            asm volatile("cp.async.wait_group 0;" ::: "memory");
        }
        __syncthreads();

        const uint32_t tA = tiles_u + (uint32_t)(s & 1) * 32768u;
        const uint32_t tB = tA + 16384u;

        ld_frags(tA, tB, 0, afr[0], bfr[0]);
#pragma unroll
        for (int kk = 0; kk < 4; ++kk) {
            const int cur = kk & 1;
            if (kk < 3) ld_frags(tA, tB, kk + 1, afr[cur ^ 1], bfr[cur ^ 1]);
#pragma unroll
            for (int mt = 0; mt < 4; ++mt)
#pragma unroll
                for (int nt = 0; nt < 4; ++nt)
                    mma_bf16(acc[mt][nt], afr[cur][mt],
                             bfr[cur][nt >> 1][(nt & 1) * 2],
                             bfr[cur][nt >> 1][(nt & 1) * 2 + 1]);
        }
        __syncthreads();
    }

    const int g = lane >> 2, tg = lane & 3;
#pragma unroll
    for (int mt = 0; mt < 4; ++mt) {
#pragma unroll
        for (int nt = 0; nt < 4; ++nt) {
            const int m0 = bm + wm * 64 + mt * 16 + g;
            const int n0 = bn + wn * 32 + nt * 8 + tg * 2;
            float v0 = acc[mt][nt][0], v1 = acc[mt][nt][1];
            float v2 = acc[mt][nt][2], v3 = acc[mt][nt][3];
            if (BIAS) {
                float bb0 = bias[n0], bb1 = bias[n0 + 1];
                v0 += bb0; v1 += bb1; v2 += bb0; v3 += bb1;
            }
            v0 *= scale; v1 *= scale; v2 *= scale; v3 *= scale;
            if (RELU) {
                v0 = fmaxf(v0, 0.f); v1 = fmaxf(v1, 0.f);
                v2 = fmaxf(v2, 0.f); v3 = fmaxf(v3, 0.f);
            }
            if (OUT_BF16) {
                __nv_bfloat16* C = (__nv_bfloat16*)Cout;
                *(__nv_bfloat162*)(C + (size_t)m0 * N + n0)       = __floats2bfloat162_rn(v0, v1);
                *(__nv_bfloat162*)(C + (size_t)(m0 + 8) * N + n0) = __floats2bfloat162_rn(v2, v3);
            } else {
                float* C = (float*)Cout;
                *(float2*)(C + (size_t)m0 * N + n0)       = make_float2(v0, v1);
                *(float2*)(C + (size_t)(m0 + 8) * N + n0) = make_float2(v2, v3);
            }
        }
    }
}

// ======================= conversion / transpose ==============================
__global__ void cvt_bf16_kernel(const float* __restrict__ in,
                                __nv_bfloat16* __restrict__ out, int n4)
{
    int i = blockIdx.x * blockDim.x + threadIdx.x;
    if (i < n4) {
        float4 v = *(const float4*)(in + i * 4);
        __nv_bfloat162* o = (__nv_bfloat162*)(out + i * 4);
        o[0] = __floats2bfloat162_rn(v.x, v.y);
        o[1] = __floats2bfloat162_rn(v.z, v.w);
    }
}

struct TransJob { const float* in; __nv_bfloat16* out; int R, C; };
struct TransJobs6 { TransJob j[6]; };

__global__ void transpose_all_kernel(TransJobs6 jobs)
{
    __shared__ float tile[32][33];
    const TransJob j = jobs.j[blockIdx.z];
    const int c0 = blockIdx.x * 32, r0 = blockIdx.y * 32;
    if (c0 >= j.C || r0 >= j.R) return;
    const int tx = threadIdx.x, ty = threadIdx.y;
#pragma unroll
    for (int i = ty; i < 32; i += 8)
        tile[i][tx] = j.in[(size_t)(r0 + i) * j.C + c0 + tx];
    __syncthreads();
#pragma unroll
    for (int i = ty; i < 32; i += 8)
        j.out[(size_t)(c0 + i) * j.R + r0 + tx] = __float2bfloat16(tile[tx][i]);
}

// ======================= normalize: fp32 in -> bf16 unit rows ================
__global__ void normalize_bf_kernel(const float* __restrict__ x,
                                    __nv_bfloat16* __restrict__ y)
{
    __shared__ float red[128];
    const int row = blockIdx.x, tid = threadIdx.x;
    const float* p = x + (size_t)row * PROJ;
    __nv_bfloat16* q = y + (size_t)row * PROJ;
    float s = 0.f;
    for (int j = tid; j < PROJ; j += 128) { float v = p[j]; s += v * v; }
    red[tid] = s; __syncthreads();
    for (int off = 64; off > 0; off >>= 1) {
        if (tid < off) red[tid] += red[tid + off];
        __syncthreads();
    }
    const float r = rsqrtf(red[0]);
    for (int j = tid; j < PROJ; j += 128) q[j] = __float2bfloat16(p[j] * r);
}

// ======================= mining + weighted CE (v2) ============================
__device__ __forceinline__ unsigned mono(float f)
{
    unsigned u = __float_as_uint(f);
    return (u & 0x80000000u) ? ~u : (u | 0x80000000u);
}

__global__ __launch_bounds__(256)
void mine_loss_kernel(const float* __restrict__ sim, const float* __restrict__ mw,
                      float* __restrict__ ce_out, int modal)
{
    __shared__ float    sh[B_SZ];        // 32 KB
    __shared__ unsigned hist[2048];      // 8 KB
    __shared__ unsigned part[256];
    __shared__ float    red[256];
    __shared__ unsigned s_prefix;
    __shared__ int      s_kth;

    const int row  = blockIdx.x;
    const int tid  = threadIdx.x;
    const int lane = tid & 31;

    const float4* srow4 = (const float4*)(sim + (size_t)row * B_SZ);
    for (int j = tid; j < B_SZ / 4; j += 256)
        *(float4*)&sh[j * 4] = srow4[j];
    __syncthreads();

    unsigned prefix = 0, pmask = 0;
    int kth = KSEL;
    const int      pshift[3] = {21, 10, 0};
    const unsigned pdmask[3] = {0x7FFu, 0x7FFu, 0x3FFu};

#pragma unroll
    for (int pass = 0; pass < 3; ++pass) {
        const int shift      = pshift[pass];
        const unsigned dmask = pdmask[pass];

        for (int i = tid; i < 2048; i += 256) hist[i] = 0;
        __syncthreads();

        for (int j = tid; j < B_SZ; j += 256) {
            float s = sh[j];
            unsigned u = (j == row || s > 9.0f) ? 0u : mono(s);
            unsigned bin = ((u & pmask) == prefix) ? ((u >> shift) & dmask) : 0xFFFFFFFFu;
            unsigned peers = __match_any_sync(0xFFFFFFFFu, bin);
            if (bin != 0xFFFFFFFFu && lane == (unsigned)(__ffs(peers) - 1))
                atomicAdd(&hist[bin], (unsigned)__popc(peers));
        }
        __syncthreads();

        unsigned loc[8];
        unsigned tot = 0;
#pragma unroll
        for (int i = 7; i >= 0; --i) { tot += hist[tid * 8 + i]; loc[i] = tot; }
        part[tid] = tot;
        __syncthreads();
#pragma unroll
        for (int off = 1; off < 256; off <<= 1) {
            unsigned u2 = (tid + off < 256) ? part[tid + off] : 0u;
            __syncthreads();
            part[tid] += u2;
            __syncthreads();
        }
        const unsigned above = part[tid] - tot;
        if (above < (unsigned)kth && loc[0] + above >= (unsigned)kth) {
            int bi = 0;
#pragma unroll
            for (int i = 7; i >= 1; --i)
                if (loc[i] + above >= (unsigned)kth) { bi = i; break; }
            const unsigned nb = (bi < 7) ? loc[bi + 1] : 0u;
            s_prefix = prefix | ((unsigned)(tid * 8 + bi) << shift);
            s_kth    = kth - (int)(nb + above);
        }
        __syncthreads();
        prefix = s_prefix; kth = s_kth;
        pmask |= (dmask << shift);
        __syncthreads();
    }
    const unsigned thr = prefix;

    float vmax = -3.402823466e38f;
    for (int j = tid; j < B_SZ; j += 256) {
        float s = sh[j];
        bool diag  = (j == row);
        bool noise = (!diag) && (s > 9.0f);
        float w;
        if (noise)                        w = 0.5f;
        else if (!diag && mono(s) >= thr) w = 1.5f;
        else                              w = 1.0f;
        float v = s * w;
        sh[j] = v;
        vmax = fmaxf(vmax, v);
    }
    red[tid] = vmax; __syncthreads();
    for (int off = 128; off > 0; off >>= 1) {
        if (tid < off) red[tid] = fmaxf(red[tid], red[tid + off]);
        __syncthreads();
    }
    const float vm = red[0];
    __syncthreads();

    float ssum = 0.f;
    for (int j = tid; j < B_SZ; j += 256) ssum += __expf(sh[j] - vm);
    red[tid] = ssum; __syncthreads();
    for (int off = 128; off > 0; off >>= 1) {
        if (tid < off) red[tid] += red[tid + off];
        __syncthreads();
    }
    if (tid == 0) {
        float lse = vm + __logf(red[0]);
        float ce  = lse - sh[row];
        ce_out[modal * B_SZ + row] = ce * mw[(size_t)row * 2 + modal];
    }
}

__global__ void finalize_kernel(const float* __restrict__ ce, float* __restrict__ out)
{
    __shared__ float red[256];
    const int tid = threadIdx.x;
    float s = 0.f;
    for (int j = tid; j < 2 * B_SZ; j += 256) s += ce[j];
    red[tid] = s; __syncthreads();
    for (int off = 128; off > 0; off >>= 1) {
        if (tid < off) red[tid] += red[tid + off];
        __syncthreads();
    }
    if (tid == 0) out[0] = red[0] * (0.5f / (float)B_SZ);
}

// ======================= launch ==============================================
extern "C" void kernel_launch(void* const* d_in, const int* in_sizes, int n_in,
                              void* d_out, int out_size)
{
    const float* id_emb = (const float*)d_in[0];
    const float* text   = (const float*)d_in[1];
    const float* vis    = (const float*)d_in[2];
    const float* mw     = (const float*)d_in[3];
    const float* Wa_t = (const float*)d_in[4];  const float* ba_t = (const float*)d_in[5];
    const float* Wa_v = (const float*)d_in[6];  const float* ba_v = (const float*)d_in[7];
    const float* W1_t = (const float*)d_in[8];  const float* b1_t = (const float*)d_in[9];
    const float* W2_t = (const float*)d_in[10]; const float* b2_t = (const float*)d_in[11];
    const float* W1_v = (const float*)d_in[12]; const float* b1_v = (const float*)d_in[13];
    const float* W2_v = (const float*)d_in[14]; const float* b2_v = (const float*)d_in[15];

    __nv_bfloat16 *wa_t, *wa_v, *w1_t, *w1_v, *w2_t, *w2_v;
    __nv_bfloat16 *id_bf, *in_bf, *feat_bf, *h_bf, *mproj, *iproj;
    float *projf, *sim, *ce;
    cudaGetSymbolAddress((void**)&wa_t, g_Wa_t);   cudaGetSymbolAddress((void**)&wa_v, g_Wa_v);
    cudaGetSymbolAddress((void**)&w1_t, g_W1_t);   cudaGetSymbolAddress((void**)&w1_v, g_W1_v);
    cudaGetSymbolAddress((void**)&w2_t, g_W2_t);   cudaGetSymbolAddress((void**)&w2_v, g_W2_v);
    cudaGetSymbolAddress((void**)&id_bf, g_id_bf); cudaGetSymbolAddress((void**)&in_bf, g_in_bf);
    cudaGetSymbolAddress((void**)&feat_bf, g_feat_bf); cudaGetSymbolAddress((void**)&h_bf, g_h_bf);
    cudaGetSymbolAddress((void**)&projf, g_projf);
    cudaGetSymbolAddress((void**)&mproj, g_mproj); cudaGetSymbolAddress((void**)&iproj, g_iproj);
    cudaGetSymbolAddress((void**)&sim, g_sim);     cudaGetSymbolAddress((void**)&ce, g_ce);

    cudaFuncSetAttribute(hmma_gemm<false, true, true>,
                         cudaFuncAttributeMaxDynamicSharedMemorySize, TC_DSMEM);
    cudaFuncSetAttribute(hmma_gemm<true, true, true>,
                         cudaFuncAttributeMaxDynamicSharedMemorySize, TC_DSMEM);
    cudaFuncSetAttribute(hmma_gemm<false, true, false>,
                         cudaFuncAttributeMaxDynamicSharedMemorySize, TC_DSMEM);
    cudaFuncSetAttribute(hmma_gemm<false, false, false>,
                         cudaFuncAttributeMaxDynamicSharedMemorySize, TC_DSMEM);

    {
        TransJobs6 jobs = {{
            { Wa_t, wa_t, 768,  HID  },
            { Wa_v, wa_v, 2048, HID  },
            { W1_t, w1_t, HID,  HID  },
            { W1_v, w1_v, HID,  HID  },
            { W2_t, w2_t, HID,  PROJ },
            { W2_v, w2_v, HID,  PROJ },
        }};
        transpose_all_kernel<<<dim3(HID / 32, 2048 / 32, 6), dim3(32, 8)>>>(jobs);
    }
    cvt_bf16_kernel<<<(B_SZ * HID / 4 + 255) / 256, 256>>>(id_emb, id_bf, B_SZ * HID / 4);

    struct Modal {
        const float* f; int kf;
        const __nv_bfloat16 *wa, *w1, *w2;
        const float *ba, *b1, *b2;
    };
    const Modal ms[2] = {
        { text,  768, wa_t, w1_t, w2_t, ba_t, b1_t, b2_t },
        { vis,  2048, wa_v, w1_v, w2_v, ba_v, b1_v, b2_v },
    };

    for (int m = 0; m < 2; m++) {
        const int KF = ms[m].kf;
        cvt_bf16_kernel<<<(B_SZ * KF / 4 + 255) / 256, 256>>>(ms[m].f, in_bf, B_SZ * KF / 4);
        hmma_gemm<false, true, true><<<dim3(HID / 128, B_SZ / 128), 256, TC_DSMEM>>>(
            in_bf, ms[m].wa, ms[m].ba, feat_bf, B_SZ, HID, KF, 1.f);
        hmma_gemm<true, true, true><<<dim3(HID / 128, B_SZ / 128), 256, TC_DSMEM>>>(
            feat_bf, ms[m].w1, ms[m].b1, h_bf, B_SZ, HID, HID, 1.f);
        hmma_gemm<false, true, false><<<dim3(PROJ / 128, B_SZ / 128), 256, TC_DSMEM>>>(
            h_bf, ms[m].w2, ms[m].b2, projf, B_SZ, PROJ, HID, 1.f);
        normalize_bf_kernel<<<B_SZ, 128>>>(projf, mproj);
        hmma_gemm<true, true, true><<<dim3(HID / 128, B_SZ / 128), 256, TC_DSMEM>>>(
            id_bf, ms[m].w1, ms[m].b1, h_bf, B_SZ, HID, HID, 1.f);
        hmma_gemm<false, true, false><<<dim3(PROJ / 128, B_SZ / 128), 256, TC_DSMEM>>>(
            h_bf, ms[m].w2, ms[m].b2, projf, B_SZ, PROJ, HID, 1.f);
        normalize_bf_kernel<<<B_SZ, 128>>>(projf, iproj);
        hmma_gemm<false, false, false><<<dim3(B_SZ / 128, B_SZ / 128), 256, TC_DSMEM>>>(
            iproj, mproj, nullptr, sim, B_SZ, B_SZ, PROJ, 10.0f);
        mine_loss_kernel<<<B_SZ, 256>>>(sim, mw, ce, m);
    }
    finalize_kernel<<<1, 256>>>(ce, (float*)d_out);
}